// round 1
// baseline (speedup 1.0000x reference)
#include <cuda_runtime.h>
#include <cuda_bf16.h>
#include <math.h>

#define D 256
#define F 1024
#define CLS 40
#define NMAX 50000
#define EMAX 300000

// ---------------- scratch (static device memory; no allocations) ----------------
__device__ float g_X[NMAX * D];
__device__ float g_Y[NMAX * D];
__device__ float g_M[NMAX * D];
__device__ float g_degout[NMAX];
__device__ float g_degin[NMAX];
__device__ float g_ns[NMAX];
__device__ float g_nd[NMAX];
__device__ float g_sum[D];
__device__ float g_sumsq[D];
__device__ float g_scale[D];
__device__ float g_shift[D];

// ---------------- elementwise helpers ----------------
__global__ void zero_k(float* __restrict__ p, int n) {
    int i = blockIdx.x * blockDim.x + threadIdx.x;
    if (i < n) p[i] = 0.0f;
}

__global__ void deg_k(const int* __restrict__ src, const int* __restrict__ dst, int E) {
    int e = blockIdx.x * blockDim.x + threadIdx.x;
    if (e < E) {
        atomicAdd(&g_degout[src[e]], 1.0f);
        atomicAdd(&g_degin[dst[e]], 1.0f);
    }
}

__global__ void norm_k(int n) {
    int i = blockIdx.x * blockDim.x + threadIdx.x;
    if (i < n) {
        g_ns[i] = rsqrtf(fmaxf(g_degout[i], 1.0f));
        g_nd[i] = rsqrtf(fmaxf(g_degin[i], 1.0f));
    }
}

// Edge scatter: M[dst] += X[src] * ns[src]   (64 threads per edge, float4 chunks)
__global__ void scatter_k(const float* __restrict__ X,
                          const int* __restrict__ src, const int* __restrict__ dst,
                          const float* __restrict__ ns,
                          float* __restrict__ Mb, int E) {
    int idx = blockIdx.x * blockDim.x + threadIdx.x;
    if (idx >= E * (D / 4)) return;
    int e = idx >> 6;        // D/4 == 64
    int c = (idx & 63) << 2; // column offset 0..252 step 4
    int s = src[e];
    int d = dst[e];
    float sc = ns[s];
    float4 v = *(const float4*)(X + (size_t)s * D + c);
    float* p = Mb + (size_t)d * D + c;
    asm volatile("red.global.add.v4.f32 [%0], {%1, %2, %3, %4};"
                 :: "l"(p), "f"(v.x * sc), "f"(v.y * sc), "f"(v.z * sc), "f"(v.w * sc)
                 : "memory");
}

// Column statistics for batchnorm: one thread per column, blocks stride rows.
__global__ void colstat_k(const float* __restrict__ X, int Nrows) {
    int col = threadIdx.x;  // blockDim.x == D
    float s = 0.0f, s2 = 0.0f;
    for (int r = blockIdx.x; r < Nrows; r += gridDim.x) {
        float v = X[(size_t)r * D + col];
        s += v;
        s2 += v * v;
    }
    atomicAdd(&g_sum[col], s);
    atomicAdd(&g_sumsq[col], s2);
}

__global__ void bnfin_k(const float* __restrict__ gamma, const float* __restrict__ beta,
                        float invN) {
    int c = threadIdx.x;  // <<<1, D>>>
    float mean = g_sum[c] * invN;
    float var = g_sumsq[c] * invN - mean * mean;
    float sc = gamma[c] * rsqrtf(var + 1e-5f);
    g_scale[c] = sc;
    g_shift[c] = beta[c] - mean * sc;
}

__global__ void bnapply_k(float* __restrict__ X, int n) {
    int i = blockIdx.x * blockDim.x + threadIdx.x;
    if (i >= n) return;
    int c = i & (D - 1);
    float v = X[i] * g_scale[c] + g_shift[c];
    X[i] = v > 0.0f ? v : expm1f(v);
}

// ---------------- tiled fp32 GEMM ----------------
// C[M,Nc] = (rs ? diag(rs) : I) * A[M,K] @ B[K,Nc] + bias
// BM=64, BN=64, BK=16, 256 threads, 4x4 microtile.
__global__ __launch_bounds__(256) void sgemm_k(
    const float* __restrict__ A, const float* __restrict__ B,
    const float* __restrict__ bias, const float* __restrict__ rs,
    float* __restrict__ C, int M, int K, int Nc) {
    __shared__ float sA[16][64];
    __shared__ float sB[16][64];

    int tid = threadIdx.x;
    int row0 = blockIdx.y * 64;
    int col0 = blockIdx.x * 64;
    int ty = tid >> 4;       // 0..15
    int tx = tid & 15;       // 0..15

    // A-load mapping: 64 rows x 16 cols
    int ar = tid >> 2;            // 0..63
    int aq = (tid & 3) << 2;      // 0,4,8,12
    // B-load mapping: 16 rows x 64 cols
    int br = tid >> 4;            // 0..15
    int bq = (tid & 15) << 2;     // 0..60

    int grow = row0 + ar;
    bool arow_ok = (grow < M);
    float scale = 1.0f;
    if (rs != nullptr && arow_ok) scale = rs[grow];

    float acc[4][4] = {};

    for (int k0 = 0; k0 < K; k0 += 16) {
        float4 av = make_float4(0.f, 0.f, 0.f, 0.f);
        if (arow_ok) av = *(const float4*)(A + (size_t)grow * K + k0 + aq);
        sA[aq + 0][ar] = av.x * scale;
        sA[aq + 1][ar] = av.y * scale;
        sA[aq + 2][ar] = av.z * scale;
        sA[aq + 3][ar] = av.w * scale;

        int bk = k0 + br;
        int bc = col0 + bq;
        float4 bv;
        if (bc + 3 < Nc) {
            bv = *(const float4*)(B + (size_t)bk * Nc + bc);
        } else {
            bv.x = (bc + 0 < Nc) ? B[(size_t)bk * Nc + bc + 0] : 0.f;
            bv.y = (bc + 1 < Nc) ? B[(size_t)bk * Nc + bc + 1] : 0.f;
            bv.z = (bc + 2 < Nc) ? B[(size_t)bk * Nc + bc + 2] : 0.f;
            bv.w = (bc + 3 < Nc) ? B[(size_t)bk * Nc + bc + 3] : 0.f;
        }
        *(float4*)&sB[br][bq] = bv;

        __syncthreads();
#pragma unroll
        for (int k = 0; k < 16; k++) {
            float4 a = *(const float4*)&sA[k][ty << 2];
            float4 b = *(const float4*)&sB[k][tx << 2];
            acc[0][0] += a.x * b.x; acc[0][1] += a.x * b.y; acc[0][2] += a.x * b.z; acc[0][3] += a.x * b.w;
            acc[1][0] += a.y * b.x; acc[1][1] += a.y * b.y; acc[1][2] += a.y * b.z; acc[1][3] += a.y * b.w;
            acc[2][0] += a.z * b.x; acc[2][1] += a.z * b.y; acc[2][2] += a.z * b.z; acc[2][3] += a.z * b.w;
            acc[3][0] += a.w * b.x; acc[3][1] += a.w * b.y; acc[3][2] += a.w * b.z; acc[3][3] += a.w * b.w;
        }
        __syncthreads();
    }

#pragma unroll
    for (int i = 0; i < 4; i++) {
        int r = row0 + (ty << 2) + i;
        if (r >= M) continue;
#pragma unroll
        for (int j = 0; j < 4; j++) {
            int c = col0 + (tx << 2) + j;
            if (c < Nc) C[(size_t)r * Nc + c] = acc[i][j] + bias[c];
        }
    }
}

// ---------------- host orchestration ----------------
static inline int cdiv(int a, int b) { return (a + b - 1) / b; }

extern "C" void kernel_launch(void* const* d_in, const int* in_sizes, int n_in,
                              void* d_out, int out_size) {
    const float* feat  = (const float*)d_in[0];
    const int*   src   = (const int*)d_in[1];
    const int*   dst   = (const int*)d_in[2];
    const float* W_fc  = (const float*)d_in[3];
    const float* b_fc  = (const float*)d_in[4];
    const float* W1    = (const float*)d_in[5];
    const float* b1    = (const float*)d_in[6];
    const float* W2    = (const float*)d_in[7];
    const float* b2    = (const float*)d_in[8];
    const float* W3    = (const float*)d_in[9];
    const float* b3    = (const float*)d_in[10];
    const float* gamma = (const float*)d_in[11];
    const float* beta  = (const float*)d_in[12];
    const float* W_lin = (const float*)d_in[13];
    const float* b_lin = (const float*)d_in[14];
    float* out = (float*)d_out;

    int N = in_sizes[0] / F;  // 50000
    int E = in_sizes[1];      // 300000

    float *pX, *pY, *pM, *pDegO, *pDegI, *pNs, *pNd, *pSum, *pSumsq;
    cudaGetSymbolAddress((void**)&pX, g_X);
    cudaGetSymbolAddress((void**)&pY, g_Y);
    cudaGetSymbolAddress((void**)&pM, g_M);
    cudaGetSymbolAddress((void**)&pDegO, g_degout);
    cudaGetSymbolAddress((void**)&pDegI, g_degin);
    cudaGetSymbolAddress((void**)&pNs, g_ns);
    cudaGetSymbolAddress((void**)&pNd, g_nd);
    cudaGetSymbolAddress((void**)&pSum, g_sum);
    cudaGetSymbolAddress((void**)&pSumsq, g_sumsq);

    const int ND = N * D;
    const int TB = 256;

    // ---- degree norms ----
    zero_k<<<cdiv(N, TB), TB>>>(pDegO, N);
    zero_k<<<cdiv(N, TB), TB>>>(pDegI, N);
    deg_k<<<cdiv(E, TB), TB>>>(src, dst, E);
    norm_k<<<cdiv(N, TB), TB>>>(N);

    // ---- FC: X = feat @ W_fc + b_fc ----
    {
        dim3 grid(cdiv(D, 64), cdiv(N, 64));
        sgemm_k<<<grid, 256>>>(feat, W_fc, b_fc, nullptr, pX, N, F, D);
    }

    // ---- layer 1: gconv(X) -> Y, then bn+elu(Y) ----
    zero_k<<<cdiv(ND, TB), TB>>>(pM, ND);
    scatter_k<<<cdiv(E * (D / 4), TB), TB>>>(pX, src, dst, pNs, pM, E);
    {
        dim3 grid(cdiv(D, 64), cdiv(N, 64));
        sgemm_k<<<grid, 256>>>(pM, W1, b1, pNd, pY, N, D, D);
    }
    zero_k<<<cdiv(2 * D, TB), TB>>>(pSum, D);      // zeros g_sum
    zero_k<<<cdiv(2 * D, TB), TB>>>(pSumsq, D);    // zeros g_sumsq
    colstat_k<<<448, D>>>(pY, N);
    bnfin_k<<<1, D>>>(gamma, beta, 1.0f / (float)N);
    bnapply_k<<<cdiv(ND, TB), TB>>>(pY, ND);

    // ---- layer 2: gconv(Y) -> X, then bn+elu(X) ----
    zero_k<<<cdiv(ND, TB), TB>>>(pM, ND);
    scatter_k<<<cdiv(E * (D / 4), TB), TB>>>(pY, src, dst, pNs, pM, E);
    {
        dim3 grid(cdiv(D, 64), cdiv(N, 64));
        sgemm_k<<<grid, 256>>>(pM, W2, b2, pNd, pX, N, D, D);
    }
    zero_k<<<cdiv(2 * D, TB), TB>>>(pSum, D);
    zero_k<<<cdiv(2 * D, TB), TB>>>(pSumsq, D);
    colstat_k<<<448, D>>>(pX, N);
    bnfin_k<<<1, D>>>(gamma, beta, 1.0f / (float)N);
    bnapply_k<<<cdiv(ND, TB), TB>>>(pX, ND);

    // ---- layer 3: gconv(X) -> out[0 : N*D] (no bn) ----
    zero_k<<<cdiv(ND, TB), TB>>>(pM, ND);
    scatter_k<<<cdiv(E * (D / 4), TB), TB>>>(pX, src, dst, pNs, pM, E);
    {
        dim3 grid(cdiv(D, 64), cdiv(N, 64));
        sgemm_k<<<grid, 256>>>(pM, W3, b3, pNd, out, N, D, D);
    }

    // ---- head: logits = x @ W_lin + b_lin -> out[N*D : N*D + N*CLS] ----
    {
        dim3 grid(cdiv(CLS, 64), cdiv(N, 64));
        sgemm_k<<<grid, 256>>>(out, W_lin, b_lin, nullptr, out + (size_t)N * D, N, D, CLS);
    }
}

// round 4
// speedup vs baseline: 1.6154x; 1.6154x over previous
#include <cuda_runtime.h>
#include <cuda_bf16.h>
#include <cstdint>
#include <math.h>

#define D 256
#define F 1024
#define CLS 40
#define NMAX 50000
#define EMAX 300000

// ---------------- scratch (static device memory; no allocations) ----------------
__device__ float g_X[NMAX * D];
__device__ float g_Y[NMAX * D];
__device__ float g_M[NMAX * D];
__device__ float g_degout[NMAX];
__device__ float g_degin[NMAX];
__device__ float g_ns[NMAX];
__device__ float g_nd[NMAX];
__device__ float g_sum[D];
__device__ float g_sumsq[D];
__device__ float g_scale[D];
__device__ float g_shift[D];

__device__ __forceinline__ uint32_t tf32r(float x) {
    uint32_t r;
    asm("cvt.rna.tf32.f32 %0, %1;" : "=r"(r) : "f"(x));
    return r;
}

// ---------------- tf32 mma.sync GEMM ----------------
// C[M,256] = diag(rs) * (A[M,K] @ W[K,256]) + bias.   K % 32 == 0.
// CTA tile 128x128x32, 8 warps (2x4), warp tile 64x32, m16n8k8 tf32 HMMA.
#define GEMM_SMEM 65536

__device__ __forceinline__ void fetch_tiles(
    const float* __restrict__ A, const float* __restrict__ W, int M, int K,
    int row0, int col0, int k0, int rbase, int c4, int kbase, int n4,
    float4 (&av)[4], float4 (&bv)[4]) {
#pragma unroll
    for (int j = 0; j < 4; j++) {
        int gr = row0 + rbase + 32 * j;
        av[j] = (gr < M) ? *(const float4*)(A + (size_t)gr * K + k0 + c4)
                         : make_float4(0.f, 0.f, 0.f, 0.f);
    }
#pragma unroll
    for (int j = 0; j < 4; j++) {
        int k = kbase + 8 * j;
        bv[j] = *(const float4*)(W + (size_t)(k0 + k) * 256 + col0 + n4);
    }
}

__device__ __forceinline__ void scatter_tiles(
    uint32_t* __restrict__ sa, uint32_t* __restrict__ sb,
    int rbase, int c4, int kbase, int n4,
    const float4 (&av)[4], const float4 (&bv)[4]) {
#pragma unroll
    for (int j = 0; j < 4; j++) {
        int r = rbase + 32 * j;  // 0..127
        int r16 = r & 15, mt = r >> 4;
        float vals[4] = {av[j].x, av[j].y, av[j].z, av[j].w};
#pragma unroll
        for (int t = 0; t < 4; t++) {
            int c = c4 + t;
            int kk = c >> 3, c8 = c & 7;
            int ln = (r16 & 7) * 4 + (c8 & 3);
            int sl = (r16 >> 3) | ((c8 >> 2) << 1);
            int tile = kk * 8 + mt;
            int lp = ln ^ ((tile >> 3) << 2);      // bank swizzle
            sa[(tile * 32 + lp) * 4 + sl] = tf32r(vals[t]);
        }
    }
#pragma unroll
    for (int j = 0; j < 4; j++) {
        int k = kbase + 8 * j;  // 0..31
        int kk = k >> 3, k8 = k & 7;
        int sl = k8 >> 2, l4 = k8 & 3;
        float vals[4] = {bv[j].x, bv[j].y, bv[j].z, bv[j].w};
#pragma unroll
        for (int t = 0; t < 4; t++) {
            int n = n4 + t;  // 0..127
            int nt = n >> 3, n8 = n & 7;
            int tile = kk * 16 + nt;
            int ln = n8 * 4 + l4;
            int lp = ln ^ ((tile & 7) << 2);       // bank swizzle
            sb[(tile * 32 + lp) * 2 + sl] = tf32r(vals[t]);
        }
    }
}

__global__ __launch_bounds__(256, 2) void mma_gemm_k(
    const float* __restrict__ A, const float* __restrict__ W,
    const float* __restrict__ bias, const float* __restrict__ rs,
    float* __restrict__ C, int M, int K) {
    extern __shared__ uint32_t dsm[];
    uint32_t* sAb = dsm;         // [2][4096]
    uint32_t* sBb = dsm + 8192;  // [2][4096]

    const int tid = threadIdx.x;
    const int lane = tid & 31;
    const int wid = tid >> 5;
    const int wm = wid >> 2, wn = wid & 3;
    const int row0 = blockIdx.y * 128;
    const int col0 = blockIdx.x * 128;

    const int c4 = (tid & 7) * 4;
    const int rbase = tid >> 3;
    const int n4 = (tid & 31) * 4;
    const int kbase = tid >> 5;

    float acc[4][4][4];
#pragma unroll
    for (int i = 0; i < 4; i++)
#pragma unroll
        for (int j = 0; j < 4; j++)
#pragma unroll
            for (int t = 0; t < 4; t++) acc[i][j][t] = 0.0f;

    const int nch = K >> 5;
    float4 av[4], bv[4];

    fetch_tiles(A, W, M, K, row0, col0, 0, rbase, c4, kbase, n4, av, bv);
    scatter_tiles(sAb, sBb, rbase, c4, kbase, n4, av, bv);
    __syncthreads();

    for (int ch = 0; ch < nch; ch++) {
        const int s = ch & 1;
        if (ch + 1 < nch)
            fetch_tiles(A, W, M, K, row0, col0, (ch + 1) << 5, rbase, c4, kbase, n4, av, bv);

        const uint32_t* sa = sAb + s * 4096;
        const uint32_t* sb = sBb + s * 4096;
#pragma unroll
        for (int kk = 0; kk < 4; kk++) {
            uint32_t af[4][4];
            uint32_t bf[4][2];
#pragma unroll
            for (int im = 0; im < 4; im++) {
                int tile = kk * 8 + wm * 4 + im;
                int lp = lane ^ ((tile >> 3) << 2);
                uint4 u = *(const uint4*)(sa + (tile * 32 + lp) * 4);
                af[im][0] = u.x; af[im][1] = u.y; af[im][2] = u.z; af[im][3] = u.w;
            }
#pragma unroll
            for (int in = 0; in < 4; in++) {
                int tile = kk * 16 + wn * 4 + in;
                int lp = lane ^ ((tile & 7) << 2);
                uint2 u = *(const uint2*)(sb + (tile * 32 + lp) * 2);
                bf[in][0] = u.x; bf[in][1] = u.y;
            }
#pragma unroll
            for (int im = 0; im < 4; im++)
#pragma unroll
                for (int in = 0; in < 4; in++)
                    asm volatile(
                        "mma.sync.aligned.m16n8k8.row.col.f32.tf32.tf32.f32 "
                        "{%0,%1,%2,%3}, {%4,%5,%6,%7}, {%8,%9}, {%0,%1,%2,%3};"
                        : "+f"(acc[im][in][0]), "+f"(acc[im][in][1]),
                          "+f"(acc[im][in][2]), "+f"(acc[im][in][3])
                        : "r"(af[im][0]), "r"(af[im][1]), "r"(af[im][2]), "r"(af[im][3]),
                          "r"(bf[in][0]), "r"(bf[in][1]));
        }
        if (ch + 1 < nch)
            scatter_tiles(sAb + (s ^ 1) * 4096, sBb + (s ^ 1) * 4096,
                          rbase, c4, kbase, n4, av, bv);
        __syncthreads();
    }

    // epilogue: row scale + bias, direct stores
    float rsl[4], rsh[4];
#pragma unroll
    for (int im = 0; im < 4; im++) {
        int rl = row0 + wm * 64 + im * 16 + (lane >> 2);
        int rh = rl + 8;
        rsl[im] = (rs != nullptr && rl < M) ? rs[rl] : 1.0f;
        rsh[im] = (rs != nullptr && rh < M) ? rs[rh] : 1.0f;
    }
#pragma unroll
    for (int im = 0; im < 4; im++) {
        int rl = row0 + wm * 64 + im * 16 + (lane >> 2);
        int rh = rl + 8;
#pragma unroll
        for (int in = 0; in < 4; in++) {
            int cc = col0 + wn * 32 + in * 8 + (lane & 3) * 2;
            float b0 = bias[cc], b1 = bias[cc + 1];
            if (rl < M) {
                float2 v = make_float2(acc[im][in][0] * rsl[im] + b0,
                                       acc[im][in][1] * rsl[im] + b1);
                *(float2*)(C + (size_t)rl * 256 + cc) = v;
            }
            if (rh < M) {
                float2 v = make_float2(acc[im][in][2] * rsh[im] + b0,
                                       acc[im][in][3] * rsh[im] + b1);
                *(float2*)(C + (size_t)rh * 256 + cc) = v;
            }
        }
    }
}

// ---------------- elementwise helpers ----------------
__global__ void zero_k(float* __restrict__ p, int n) {
    int i = blockIdx.x * blockDim.x + threadIdx.x;
    if (i < n) p[i] = 0.0f;
}

__global__ void zero4_k(float4* __restrict__ p, int n4) {
    int i = blockIdx.x * blockDim.x + threadIdx.x;
    if (i < n4) p[i] = make_float4(0.f, 0.f, 0.f, 0.f);
}

__global__ void deg_k(const int* __restrict__ src, const int* __restrict__ dst, int E) {
    int e = blockIdx.x * blockDim.x + threadIdx.x;
    if (e < E) {
        atomicAdd(&g_degout[src[e]], 1.0f);
        atomicAdd(&g_degin[dst[e]], 1.0f);
    }
}

__global__ void norm_k(int n) {
    int i = blockIdx.x * blockDim.x + threadIdx.x;
    if (i < n) {
        g_ns[i] = rsqrtf(fmaxf(g_degout[i], 1.0f));
        g_nd[i] = rsqrtf(fmaxf(g_degin[i], 1.0f));
    }
}

// Edge scatter: M[dst] += X[src] * ns[src]   (64 threads per edge, float4 chunks)
__global__ void scatter_k(const float* __restrict__ X,
                          const int* __restrict__ src, const int* __restrict__ dst,
                          const float* __restrict__ ns,
                          float* __restrict__ Mb, int E) {
    int idx = blockIdx.x * blockDim.x + threadIdx.x;
    if (idx >= E * (D / 4)) return;
    int e = idx >> 6;
    int c = (idx & 63) << 2;
    int s = src[e];
    int d = dst[e];
    float sc = ns[s];
    float4 v = *(const float4*)(X + (size_t)s * D + c);
    float* p = Mb + (size_t)d * D + c;
    asm volatile("red.global.add.v4.f32 [%0], {%1, %2, %3, %4};"
                 :: "l"(p), "f"(v.x * sc), "f"(v.y * sc), "f"(v.z * sc), "f"(v.w * sc)
                 : "memory");
}

__global__ void colstat_k(const float* __restrict__ X, int Nrows) {
    int col = threadIdx.x;
    float s = 0.0f, s2 = 0.0f;
    for (int r = blockIdx.x; r < Nrows; r += gridDim.x) {
        float v = X[(size_t)r * D + col];
        s += v;
        s2 += v * v;
    }
    atomicAdd(&g_sum[col], s);
    atomicAdd(&g_sumsq[col], s2);
}

__global__ void bnfin_k(const float* __restrict__ gamma, const float* __restrict__ beta,
                        float invN) {
    int c = threadIdx.x;
    float mean = g_sum[c] * invN;
    float var = g_sumsq[c] * invN - mean * mean;
    float sc = gamma[c] * rsqrtf(var + 1e-5f);
    g_scale[c] = sc;
    g_shift[c] = beta[c] - mean * sc;
}

__global__ void bnapply_k(float* __restrict__ X, int n) {
    int i = blockIdx.x * blockDim.x + threadIdx.x;
    if (i >= n) return;
    int c = i & (D - 1);
    float v = X[i] * g_scale[c] + g_shift[c];
    X[i] = v > 0.0f ? v : expm1f(v);
}

// ---------------- fp32 GEMM (head only, Nc=40) ----------------
__global__ __launch_bounds__(256) void sgemm_k(
    const float* __restrict__ A, const float* __restrict__ B,
    const float* __restrict__ bias, const float* __restrict__ rs,
    float* __restrict__ C, int M, int K, int Nc) {
    __shared__ float sA[16][64];
    __shared__ float sB[16][64];
    int tid = threadIdx.x;
    int row0 = blockIdx.y * 64;
    int col0 = blockIdx.x * 64;
    int ty = tid >> 4;
    int tx = tid & 15;
    int ar = tid >> 2;
    int aq = (tid & 3) << 2;
    int br = tid >> 4;
    int bq = (tid & 15) << 2;
    int grow = row0 + ar;
    bool arow_ok = (grow < M);
    float scale = 1.0f;
    if (rs != nullptr && arow_ok) scale = rs[grow];
    float acc[4][4] = {};
    for (int k0 = 0; k0 < K; k0 += 16) {
        float4 av = make_float4(0.f, 0.f, 0.f, 0.f);
        if (arow_ok) av = *(const float4*)(A + (size_t)grow * K + k0 + aq);
        sA[aq + 0][ar] = av.x * scale;
        sA[aq + 1][ar] = av.y * scale;
        sA[aq + 2][ar] = av.z * scale;
        sA[aq + 3][ar] = av.w * scale;
        int bk = k0 + br;
        int bc = col0 + bq;
        float4 bv;
        if (bc + 3 < Nc) {
            bv = *(const float4*)(B + (size_t)bk * Nc + bc);
        } else {
            bv.x = (bc + 0 < Nc) ? B[(size_t)bk * Nc + bc + 0] : 0.f;
            bv.y = (bc + 1 < Nc) ? B[(size_t)bk * Nc + bc + 1] : 0.f;
            bv.z = (bc + 2 < Nc) ? B[(size_t)bk * Nc + bc + 2] : 0.f;
            bv.w = (bc + 3 < Nc) ? B[(size_t)bk * Nc + bc + 3] : 0.f;
        }
        *(float4*)&sB[br][bq] = bv;
        __syncthreads();
#pragma unroll
        for (int k = 0; k < 16; k++) {
            float4 a = *(const float4*)&sA[k][ty << 2];
            float4 b = *(const float4*)&sB[k][tx << 2];
            acc[0][0] += a.x * b.x; acc[0][1] += a.x * b.y; acc[0][2] += a.x * b.z; acc[0][3] += a.x * b.w;
            acc[1][0] += a.y * b.x; acc[1][1] += a.y * b.y; acc[1][2] += a.y * b.z; acc[1][3] += a.y * b.w;
            acc[2][0] += a.z * b.x; acc[2][1] += a.z * b.y; acc[2][2] += a.z * b.z; acc[2][3] += a.z * b.w;
            acc[3][0] += a.w * b.x; acc[3][1] += a.w * b.y; acc[3][2] += a.w * b.z; acc[3][3] += a.w * b.w;
        }
        __syncthreads();
    }
#pragma unroll
    for (int i = 0; i < 4; i++) {
        int r = row0 + (ty << 2) + i;
        if (r >= M) continue;
#pragma unroll
        for (int j = 0; j < 4; j++) {
            int c = col0 + (tx << 2) + j;
            if (c < Nc) C[(size_t)r * Nc + c] = acc[i][j] + bias[c];
        }
    }
}

// ---------------- host orchestration ----------------
static inline int cdiv(int a, int b) { return (a + b - 1) / b; }

extern "C" void kernel_launch(void* const* d_in, const int* in_sizes, int n_in,
                              void* d_out, int out_size) {
    const float* feat  = (const float*)d_in[0];
    const int*   src   = (const int*)d_in[1];
    const int*   dst   = (const int*)d_in[2];
    const float* W_fc  = (const float*)d_in[3];
    const float* b_fc  = (const float*)d_in[4];
    const float* W1    = (const float*)d_in[5];
    const float* b1    = (const float*)d_in[6];
    const float* W2    = (const float*)d_in[7];
    const float* b2    = (const float*)d_in[8];
    const float* W3    = (const float*)d_in[9];
    const float* b3    = (const float*)d_in[10];
    const float* gamma = (const float*)d_in[11];
    const float* beta  = (const float*)d_in[12];
    const float* W_lin = (const float*)d_in[13];
    const float* b_lin = (const float*)d_in[14];
    float* out = (float*)d_out;

    int N = in_sizes[0] / F;  // 50000
    int E = in_sizes[1];      // 300000

    cudaFuncSetAttribute(mma_gemm_k, cudaFuncAttributeMaxDynamicSharedMemorySize, GEMM_SMEM);

    float *pX, *pY, *pM, *pDegO, *pDegI, *pNs, *pNd, *pSum, *pSumsq;
    cudaGetSymbolAddress((void**)&pX, g_X);
    cudaGetSymbolAddress((void**)&pY, g_Y);
    cudaGetSymbolAddress((void**)&pM, g_M);
    cudaGetSymbolAddress((void**)&pDegO, g_degout);
    cudaGetSymbolAddress((void**)&pDegI, g_degin);
    cudaGetSymbolAddress((void**)&pNs, g_ns);
    cudaGetSymbolAddress((void**)&pNd, g_nd);
    cudaGetSymbolAddress((void**)&pSum, g_sum);
    cudaGetSymbolAddress((void**)&pSumsq, g_sumsq);

    const int ND = N * D;
    const int TB = 256;
    const dim3 ggrid(2, cdiv(N, 128));

    // ---- degree norms ----
    zero_k<<<cdiv(N, TB), TB>>>(pDegO, N);
    zero_k<<<cdiv(N, TB), TB>>>(pDegI, N);
    deg_k<<<cdiv(E, TB), TB>>>(src, dst, E);
    norm_k<<<cdiv(N, TB), TB>>>(N);

    // ---- FC: X = feat @ W_fc + b_fc ----
    mma_gemm_k<<<ggrid, 256, GEMM_SMEM>>>(feat, W_fc, b_fc, nullptr, pX, N, F);

    // ---- layer 1 ----
    zero4_k<<<cdiv(ND / 4, TB), TB>>>((float4*)pM, ND / 4);
    scatter_k<<<cdiv(E * (D / 4), TB), TB>>>(pX, src, dst, pNs, pM, E);
    mma_gemm_k<<<ggrid, 256, GEMM_SMEM>>>(pM, W1, b1, pNd, pY, N, D);
    zero_k<<<1, TB>>>(pSum, D);
    zero_k<<<1, TB>>>(pSumsq, D);
    colstat_k<<<448, D>>>(pY, N);
    bnfin_k<<<1, D>>>(gamma, beta, 1.0f / (float)N);
    bnapply_k<<<cdiv(ND, TB), TB>>>(pY, ND);

    // ---- layer 2 ----
    zero4_k<<<cdiv(ND / 4, TB), TB>>>((float4*)pM, ND / 4);
    scatter_k<<<cdiv(E * (D / 4), TB), TB>>>(pY, src, dst, pNs, pM, E);
    mma_gemm_k<<<ggrid, 256, GEMM_SMEM>>>(pM, W2, b2, pNd, pX, N, D);
    zero_k<<<1, TB>>>(pSum, D);
    zero_k<<<1, TB>>>(pSumsq, D);
    colstat_k<<<448, D>>>(pX, N);
    bnfin_k<<<1, D>>>(gamma, beta, 1.0f / (float)N);
    bnapply_k<<<cdiv(ND, TB), TB>>>(pX, ND);

    // ---- layer 3: gconv(X) -> out[0 : N*D] ----
    zero4_k<<<cdiv(ND / 4, TB), TB>>>((float4*)pM, ND / 4);
    scatter_k<<<cdiv(E * (D / 4), TB), TB>>>(pX, src, dst, pNs, pM, E);
    mma_gemm_k<<<ggrid, 256, GEMM_SMEM>>>(pM, W3, b3, pNd, out, N, D);

    // ---- head: logits = x @ W_lin + b_lin ----
    {
        dim3 grid(cdiv(CLS, 64), cdiv(N, 64));
        sgemm_k<<<grid, 256>>>(out, W_lin, b_lin, nullptr, out + (size_t)N * D, N, D, CLS);
    }
}

// round 5
// speedup vs baseline: 1.9188x; 1.1878x over previous
#include <cuda_runtime.h>
#include <cuda_bf16.h>
#include <cstdint>
#include <math.h>

#define D 256
#define F 1024
#define CLS 40
#define NMAX 50000
#define EMAX 300000

// ---------------- scratch (static device memory; no allocations) ----------------
__device__ float g_X[NMAX * D];
__device__ float g_Y[NMAX * D];
__device__ float g_M[NMAX * D];
__device__ float g_degout[NMAX];
__device__ float g_degin[NMAX];
__device__ float g_ns[NMAX];
__device__ float g_nd[NMAX];
__device__ float g_sum[D];
__device__ float g_sumsq[D];
__device__ float g_scale[D];
__device__ float g_shift[D];
// CSR by dst
__device__ int g_cnt[NMAX];
__device__ int g_rowptr[NMAX + 1];
__device__ int g_cursor[NMAX];
__device__ int g_esrc[EMAX];
__device__ int g_bsum[256];
__device__ int g_boff[256];

__device__ __forceinline__ uint32_t tf32r(float x) {
    uint32_t r;
    asm("cvt.rna.tf32.f32 %0, %1;" : "=r"(r) : "f"(x));
    return r;
}

// ---------------- tf32 mma.sync GEMM (Nc=256) ----------------
// C[M,256] = diag(rs) * (A[M,K] @ W[K,256]) + bias.   K % 32 == 0.
#define GEMM_SMEM 65536

__device__ __forceinline__ void fetch_tiles(
    const float* __restrict__ A, const float* __restrict__ W, int M, int K,
    int row0, int col0, int k0, int rbase, int c4, int kbase, int n4,
    float4 (&av)[4], float4 (&bv)[4]) {
#pragma unroll
    for (int j = 0; j < 4; j++) {
        int gr = row0 + rbase + 32 * j;
        av[j] = (gr < M) ? *(const float4*)(A + (size_t)gr * K + k0 + c4)
                         : make_float4(0.f, 0.f, 0.f, 0.f);
    }
#pragma unroll
    for (int j = 0; j < 4; j++) {
        int k = kbase + 8 * j;
        bv[j] = *(const float4*)(W + (size_t)(k0 + k) * 256 + col0 + n4);
    }
}

__device__ __forceinline__ void scatter_tiles(
    uint32_t* __restrict__ sa, uint32_t* __restrict__ sb,
    int rbase, int c4, int kbase, int n4,
    const float4 (&av)[4], const float4 (&bv)[4]) {
#pragma unroll
    for (int j = 0; j < 4; j++) {
        int r = rbase + 32 * j;
        int r16 = r & 15, mt = r >> 4;
        float vals[4] = {av[j].x, av[j].y, av[j].z, av[j].w};
#pragma unroll
        for (int t = 0; t < 4; t++) {
            int c = c4 + t;
            int kk = c >> 3, c8 = c & 7;
            int ln = (r16 & 7) * 4 + (c8 & 3);
            int sl = (r16 >> 3) | ((c8 >> 2) << 1);
            int tile = kk * 8 + mt;
            int lp = ln ^ ((tile >> 3) << 2);
            sa[(tile * 32 + lp) * 4 + sl] = tf32r(vals[t]);
        }
    }
#pragma unroll
    for (int j = 0; j < 4; j++) {
        int k = kbase + 8 * j;
        int kk = k >> 3, k8 = k & 7;
        int sl = k8 >> 2, l4 = k8 & 3;
        float vals[4] = {bv[j].x, bv[j].y, bv[j].z, bv[j].w};
#pragma unroll
        for (int t = 0; t < 4; t++) {
            int n = n4 + t;
            int nt = n >> 3, n8 = n & 7;
            int tile = kk * 16 + nt;
            int ln = n8 * 4 + l4;
            int lp = ln ^ ((tile & 7) << 2);
            sb[(tile * 32 + lp) * 2 + sl] = tf32r(vals[t]);
        }
    }
}

__global__ __launch_bounds__(256, 2) void mma_gemm_k(
    const float* __restrict__ A, const float* __restrict__ W,
    const float* __restrict__ bias, const float* __restrict__ rs,
    float* __restrict__ C, int M, int K) {
    extern __shared__ uint32_t dsm[];
    uint32_t* sAb = dsm;
    uint32_t* sBb = dsm + 8192;

    const int tid = threadIdx.x;
    const int lane = tid & 31;
    const int wid = tid >> 5;
    const int wm = wid >> 2, wn = wid & 3;
    const int row0 = blockIdx.y * 128;
    const int col0 = blockIdx.x * 128;

    const int c4 = (tid & 7) * 4;
    const int rbase = tid >> 3;
    const int n4 = (tid & 31) * 4;
    const int kbase = tid >> 5;

    float acc[4][4][4];
#pragma unroll
    for (int i = 0; i < 4; i++)
#pragma unroll
        for (int j = 0; j < 4; j++)
#pragma unroll
            for (int t = 0; t < 4; t++) acc[i][j][t] = 0.0f;

    const int nch = K >> 5;
    float4 av[4], bv[4];

    fetch_tiles(A, W, M, K, row0, col0, 0, rbase, c4, kbase, n4, av, bv);
    scatter_tiles(sAb, sBb, rbase, c4, kbase, n4, av, bv);
    __syncthreads();

    for (int ch = 0; ch < nch; ch++) {
        const int s = ch & 1;
        if (ch + 1 < nch)
            fetch_tiles(A, W, M, K, row0, col0, (ch + 1) << 5, rbase, c4, kbase, n4, av, bv);

        const uint32_t* sa = sAb + s * 4096;
        const uint32_t* sb = sBb + s * 4096;
#pragma unroll
        for (int kk = 0; kk < 4; kk++) {
            uint32_t af[4][4];
            uint32_t bf[4][2];
#pragma unroll
            for (int im = 0; im < 4; im++) {
                int tile = kk * 8 + wm * 4 + im;
                int lp = lane ^ ((tile >> 3) << 2);
                uint4 u = *(const uint4*)(sa + (tile * 32 + lp) * 4);
                af[im][0] = u.x; af[im][1] = u.y; af[im][2] = u.z; af[im][3] = u.w;
            }
#pragma unroll
            for (int in = 0; in < 4; in++) {
                int tile = kk * 16 + wn * 4 + in;
                int lp = lane ^ ((tile & 7) << 2);
                uint2 u = *(const uint2*)(sb + (tile * 32 + lp) * 2);
                bf[in][0] = u.x; bf[in][1] = u.y;
            }
#pragma unroll
            for (int im = 0; im < 4; im++)
#pragma unroll
                for (int in = 0; in < 4; in++)
                    asm volatile(
                        "mma.sync.aligned.m16n8k8.row.col.f32.tf32.tf32.f32 "
                        "{%0,%1,%2,%3}, {%4,%5,%6,%7}, {%8,%9}, {%0,%1,%2,%3};"
                        : "+f"(acc[im][in][0]), "+f"(acc[im][in][1]),
                          "+f"(acc[im][in][2]), "+f"(acc[im][in][3])
                        : "r"(af[im][0]), "r"(af[im][1]), "r"(af[im][2]), "r"(af[im][3]),
                          "r"(bf[in][0]), "r"(bf[in][1]));
        }
        if (ch + 1 < nch)
            scatter_tiles(sAb + (s ^ 1) * 4096, sBb + (s ^ 1) * 4096,
                          rbase, c4, kbase, n4, av, bv);
        __syncthreads();
    }

    float rsl[4], rsh[4];
#pragma unroll
    for (int im = 0; im < 4; im++) {
        int rl = row0 + wm * 64 + im * 16 + (lane >> 2);
        int rh = rl + 8;
        rsl[im] = (rs != nullptr && rl < M) ? rs[rl] : 1.0f;
        rsh[im] = (rs != nullptr && rh < M) ? rs[rh] : 1.0f;
    }
#pragma unroll
    for (int im = 0; im < 4; im++) {
        int rl = row0 + wm * 64 + im * 16 + (lane >> 2);
        int rh = rl + 8;
#pragma unroll
        for (int in = 0; in < 4; in++) {
            int cc = col0 + wn * 32 + in * 8 + (lane & 3) * 2;
            float b0 = bias[cc], b1 = bias[cc + 1];
            if (rl < M) {
                float2 v = make_float2(acc[im][in][0] * rsl[im] + b0,
                                       acc[im][in][1] * rsl[im] + b1);
                *(float2*)(C + (size_t)rl * 256 + cc) = v;
            }
            if (rh < M) {
                float2 v = make_float2(acc[im][in][2] * rsh[im] + b0,
                                       acc[im][in][3] * rsh[im] + b1);
                *(float2*)(C + (size_t)rh * 256 + cc) = v;
            }
        }
    }
}

// ---------------- tf32 mma head (K=256, Nc=40, padded to 64) ----------------
#define HEAD_SMEM 49152
__global__ __launch_bounds__(256, 2) void head_mma_k(
    const float* __restrict__ A, const float* __restrict__ W,
    const float* __restrict__ bias, float* __restrict__ C, int M) {
    extern __shared__ uint32_t hsm[];
    uint32_t* sAb = hsm;          // 2 x 4096
    uint32_t* sBb = hsm + 8192;   // 2 x 2048

    const int tid = threadIdx.x;
    const int lane = tid & 31;
    const int wid = tid >> 5;
    const int wm = wid >> 2, wn = wid & 3;
    const int row0 = blockIdx.y * 128;

    const int c4 = (tid & 7) * 4;
    const int rbase = tid >> 3;
    const int bn4 = (tid & 15) * 4;   // 0..60
    const int bkbase = tid >> 4;      // 0..15

    float acc[4][2][4];
#pragma unroll
    for (int i = 0; i < 4; i++)
#pragma unroll
        for (int j = 0; j < 2; j++)
#pragma unroll
            for (int t = 0; t < 4; t++) acc[i][j][t] = 0.0f;

    float4 av[4], bv[2];

    auto fetchH = [&](int k0) {
#pragma unroll
        for (int j = 0; j < 4; j++) {
            int gr = row0 + rbase + 32 * j;
            av[j] = (gr < M) ? *(const float4*)(A + (size_t)gr * 256 + k0 + c4)
                             : make_float4(0.f, 0.f, 0.f, 0.f);
        }
#pragma unroll
        for (int j = 0; j < 2; j++) {
            int k = bkbase + 16 * j;
            bv[j] = (bn4 < CLS) ? *(const float4*)(W + (size_t)(k0 + k) * CLS + bn4)
                                : make_float4(0.f, 0.f, 0.f, 0.f);
        }
    };
    auto scatH = [&](uint32_t* sa, uint32_t* sb) {
#pragma unroll
        for (int j = 0; j < 4; j++) {
            int r = rbase + 32 * j;
            int r16 = r & 15, mt = r >> 4;
            float vals[4] = {av[j].x, av[j].y, av[j].z, av[j].w};
#pragma unroll
            for (int t = 0; t < 4; t++) {
                int c = c4 + t;
                int kk = c >> 3, c8 = c & 7;
                int ln = (r16 & 7) * 4 + (c8 & 3);
                int sl = (r16 >> 3) | ((c8 >> 2) << 1);
                int tile = kk * 8 + mt;
                int lp = ln ^ ((tile >> 3) << 2);
                sa[(tile * 32 + lp) * 4 + sl] = tf32r(vals[t]);
            }
        }
#pragma unroll
        for (int j = 0; j < 2; j++) {
            int k = bkbase + 16 * j;
            int kk = k >> 3, k8 = k & 7;
            int sl = k8 >> 2, l4 = k8 & 3;
            float vals[4] = {bv[j].x, bv[j].y, bv[j].z, bv[j].w};
#pragma unroll
            for (int t = 0; t < 4; t++) {
                int n = bn4 + t;
                int nt = n >> 3, n8 = n & 7;
                int tile = kk * 8 + nt;
                int ln = n8 * 4 + l4;
                int lp = ln ^ ((tile & 7) << 2);
                sb[(tile * 32 + lp) * 2 + sl] = tf32r(vals[t]);
            }
        }
    };

    fetchH(0);
    scatH(sAb, sBb);
    __syncthreads();

#pragma unroll 1
    for (int ch = 0; ch < 8; ch++) {
        const int s = ch & 1;
        if (ch + 1 < 8) fetchH((ch + 1) << 5);
        const uint32_t* sa = sAb + s * 4096;
        const uint32_t* sb = sBb + s * 2048;
#pragma unroll
        for (int kk = 0; kk < 4; kk++) {
            uint32_t af[4][4];
            uint32_t bf[2][2];
#pragma unroll
            for (int im = 0; im < 4; im++) {
                int tile = kk * 8 + wm * 4 + im;
                int lp = lane ^ ((tile >> 3) << 2);
                uint4 u = *(const uint4*)(sa + (tile * 32 + lp) * 4);
                af[im][0] = u.x; af[im][1] = u.y; af[im][2] = u.z; af[im][3] = u.w;
            }
#pragma unroll
            for (int in = 0; in < 2; in++) {
                int tile = kk * 8 + wn * 2 + in;
                int lp = lane ^ ((tile & 7) << 2);
                uint2 u = *(const uint2*)(sb + (tile * 32 + lp) * 2);
                bf[in][0] = u.x; bf[in][1] = u.y;
            }
#pragma unroll
            for (int im = 0; im < 4; im++)
#pragma unroll
                for (int in = 0; in < 2; in++)
                    asm volatile(
                        "mma.sync.aligned.m16n8k8.row.col.f32.tf32.tf32.f32 "
                        "{%0,%1,%2,%3}, {%4,%5,%6,%7}, {%8,%9}, {%0,%1,%2,%3};"
                        : "+f"(acc[im][in][0]), "+f"(acc[im][in][1]),
                          "+f"(acc[im][in][2]), "+f"(acc[im][in][3])
                        : "r"(af[im][0]), "r"(af[im][1]), "r"(af[im][2]), "r"(af[im][3]),
                          "r"(bf[in][0]), "r"(bf[in][1]));
        }
        if (ch + 1 < 8) scatH(sAb + (s ^ 1) * 4096, sBb + (s ^ 1) * 2048);
        __syncthreads();
    }

#pragma unroll
    for (int im = 0; im < 4; im++) {
        int rl = row0 + wm * 64 + im * 16 + (lane >> 2);
        int rh = rl + 8;
#pragma unroll
        for (int in = 0; in < 2; in++) {
            int cc = wn * 16 + in * 8 + (lane & 3) * 2;
            if (cc >= CLS) continue;
            float b0 = bias[cc], b1 = bias[cc + 1];
            if (rl < M) {
                float2 v = make_float2(acc[im][in][0] + b0, acc[im][in][1] + b1);
                *(float2*)(C + (size_t)rl * CLS + cc) = v;
            }
            if (rh < M) {
                float2 v = make_float2(acc[im][in][2] + b0, acc[im][in][3] + b1);
                *(float2*)(C + (size_t)rh * CLS + cc) = v;
            }
        }
    }
}

// ---------------- CSR build ----------------
__global__ void zero_k(float* __restrict__ p, int n) {
    int i = blockIdx.x * blockDim.x + threadIdx.x;
    if (i < n) p[i] = 0.0f;
}
__global__ void zeroi_k(int* __restrict__ p, int n) {
    int i = blockIdx.x * blockDim.x + threadIdx.x;
    if (i < n) p[i] = 0;
}

__global__ void deg_k(const int* __restrict__ src, const int* __restrict__ dst, int E) {
    int e = blockIdx.x * blockDim.x + threadIdx.x;
    if (e < E) {
        atomicAdd(&g_degout[src[e]], 1.0f);
        atomicAdd(&g_degin[dst[e]], 1.0f);
        atomicAdd(&g_cnt[dst[e]], 1);
    }
}

__global__ void norm_k(int n) {
    int i = blockIdx.x * blockDim.x + threadIdx.x;
    if (i < n) {
        g_ns[i] = rsqrtf(fmaxf(g_degout[i], 1.0f));
        g_nd[i] = rsqrtf(fmaxf(g_degin[i], 1.0f));
    }
}

__global__ void scan1_k(int Nn) {
    __shared__ int sh[256];
    int i = blockIdx.x * 256 + threadIdx.x;
    int v = (i < Nn) ? g_cnt[i] : 0;
    sh[threadIdx.x] = v;
    __syncthreads();
    for (int off = 1; off < 256; off <<= 1) {
        int t = (threadIdx.x >= off) ? sh[threadIdx.x - off] : 0;
        __syncthreads();
        sh[threadIdx.x] += t;
        __syncthreads();
    }
    if (i < Nn) g_rowptr[i] = sh[threadIdx.x] - v;  // block-local exclusive
    if (threadIdx.x == 255) g_bsum[blockIdx.x] = sh[255];
}

__global__ void scan2_k(int nb) {
    __shared__ int sh[256];
    int v = (threadIdx.x < nb) ? g_bsum[threadIdx.x] : 0;
    sh[threadIdx.x] = v;
    __syncthreads();
    for (int off = 1; off < 256; off <<= 1) {
        int t = (threadIdx.x >= off) ? sh[threadIdx.x - off] : 0;
        __syncthreads();
        sh[threadIdx.x] += t;
        __syncthreads();
    }
    g_boff[threadIdx.x] = sh[threadIdx.x] - v;
}

__global__ void scan3_k(int Nn, int E) {
    int i = blockIdx.x * 256 + threadIdx.x;
    if (i < Nn) {
        int r = g_rowptr[i] + g_boff[blockIdx.x];
        g_rowptr[i] = r;
        g_cursor[i] = r;
    }
    if (i == 0) g_rowptr[Nn] = E;
}

__global__ void fill_k(const int* __restrict__ src, const int* __restrict__ dst, int E) {
    int e = blockIdx.x * blockDim.x + threadIdx.x;
    if (e < E) {
        int pos = atomicAdd(&g_cursor[dst[e]], 1);
        g_esrc[pos] = src[e];
    }
}

// ---------------- CSR gather SpMM: Mo[n] = nd[n] * sum_{e: dst=n} ns[src]*X[src] ----
__global__ __launch_bounds__(256) void spmm_k(const float* __restrict__ X,
                                              float* __restrict__ Mo, int Nn) {
    int node = blockIdx.x * 4 + (threadIdx.x >> 6);
    if (node >= Nn) return;
    int t4 = (threadIdx.x & 63) << 2;
    int beg = g_rowptr[node], end = g_rowptr[node + 1];
    float4 a = make_float4(0.f, 0.f, 0.f, 0.f);
    for (int j = beg; j < end; j++) {
        int s = g_esrc[j];
        float sc = g_ns[s];
        float4 v = *(const float4*)(X + (size_t)s * D + t4);
        a.x += v.x * sc; a.y += v.y * sc; a.z += v.z * sc; a.w += v.w * sc;
    }
    float nd = g_nd[node];
    a.x *= nd; a.y *= nd; a.z *= nd; a.w *= nd;
    *(float4*)(Mo + (size_t)node * D + t4) = a;
}

// ---------------- batchnorm ----------------
__global__ void colstat_k(const float* __restrict__ X, int Nrows) {
    int col = threadIdx.x;
    float s = 0.0f, s2 = 0.0f;
    for (int r = blockIdx.x; r < Nrows; r += gridDim.x) {
        float v = X[(size_t)r * D + col];
        s += v;
        s2 += v * v;
    }
    atomicAdd(&g_sum[col], s);
    atomicAdd(&g_sumsq[col], s2);
}

__global__ void bnfin_k(const float* __restrict__ gamma, const float* __restrict__ beta,
                        float invN) {
    int c = threadIdx.x;
    float mean = g_sum[c] * invN;
    float var = g_sumsq[c] * invN - mean * mean;
    float sc = gamma[c] * rsqrtf(var + 1e-5f);
    g_scale[c] = sc;
    g_shift[c] = beta[c] - mean * sc;
}

__device__ __forceinline__ float elu1(float v) { return v > 0.0f ? v : expm1f(v); }

__global__ void bnapply4_k(float4* __restrict__ X, int n4) {
    int i = blockIdx.x * blockDim.x + threadIdx.x;
    if (i >= n4) return;
    int c = (i & 63) << 2;
    float4 v = X[i];
    v.x = elu1(v.x * g_scale[c + 0] + g_shift[c + 0]);
    v.y = elu1(v.y * g_scale[c + 1] + g_shift[c + 1]);
    v.z = elu1(v.z * g_scale[c + 2] + g_shift[c + 2]);
    v.w = elu1(v.w * g_scale[c + 3] + g_shift[c + 3]);
    X[i] = v;
}

// ---------------- host orchestration ----------------
static inline int cdiv(int a, int b) { return (a + b - 1) / b; }

extern "C" void kernel_launch(void* const* d_in, const int* in_sizes, int n_in,
                              void* d_out, int out_size) {
    const float* feat  = (const float*)d_in[0];
    const int*   src   = (const int*)d_in[1];
    const int*   dst   = (const int*)d_in[2];
    const float* W_fc  = (const float*)d_in[3];
    const float* b_fc  = (const float*)d_in[4];
    const float* W1    = (const float*)d_in[5];
    const float* b1    = (const float*)d_in[6];
    const float* W2    = (const float*)d_in[7];
    const float* b2    = (const float*)d_in[8];
    const float* W3    = (const float*)d_in[9];
    const float* b3    = (const float*)d_in[10];
    const float* gamma = (const float*)d_in[11];
    const float* beta  = (const float*)d_in[12];
    const float* W_lin = (const float*)d_in[13];
    const float* b_lin = (const float*)d_in[14];
    float* out = (float*)d_out;

    int N = in_sizes[0] / F;  // 50000
    int E = in_sizes[1];      // 300000

    cudaFuncSetAttribute(mma_gemm_k, cudaFuncAttributeMaxDynamicSharedMemorySize, GEMM_SMEM);
    cudaFuncSetAttribute(head_mma_k, cudaFuncAttributeMaxDynamicSharedMemorySize, HEAD_SMEM);

    float *pX, *pY, *pM, *pDegO, *pDegI, *pSum, *pSumsq;
    int *pCnt;
    cudaGetSymbolAddress((void**)&pX, g_X);
    cudaGetSymbolAddress((void**)&pY, g_Y);
    cudaGetSymbolAddress((void**)&pM, g_M);
    cudaGetSymbolAddress((void**)&pDegO, g_degout);
    cudaGetSymbolAddress((void**)&pDegI, g_degin);
    cudaGetSymbolAddress((void**)&pSum, g_sum);
    cudaGetSymbolAddress((void**)&pSumsq, g_sumsq);
    cudaGetSymbolAddress((void**)&pCnt, g_cnt);

    const int ND = N * D;
    const int TB = 256;
    const int nb = cdiv(N, 256);
    const dim3 ggrid(2, cdiv(N, 128));
    const dim3 hgrid(1, cdiv(N, 128));
    const int sgrid = cdiv(N, 4);

    // ---- degree norms + CSR build ----
    zero_k<<<cdiv(N, TB), TB>>>(pDegO, N);
    zero_k<<<cdiv(N, TB), TB>>>(pDegI, N);
    zeroi_k<<<cdiv(N, TB), TB>>>(pCnt, N);
    deg_k<<<cdiv(E, TB), TB>>>(src, dst, E);
    norm_k<<<cdiv(N, TB), TB>>>(N);
    scan1_k<<<nb, 256>>>(N);
    scan2_k<<<1, 256>>>(nb);
    scan3_k<<<nb, 256>>>(N, E);
    fill_k<<<cdiv(E, TB), TB>>>(src, dst, E);

    // ---- FC: X = feat @ W_fc + b_fc ----
    mma_gemm_k<<<ggrid, 256, GEMM_SMEM>>>(feat, W_fc, b_fc, nullptr, pX, N, F);

    // ---- layer 1 ----
    spmm_k<<<sgrid, 256>>>(pX, pM, N);
    mma_gemm_k<<<ggrid, 256, GEMM_SMEM>>>(pM, W1, b1, nullptr, pY, N, D);
    zero_k<<<1, TB>>>(pSum, D);
    zero_k<<<1, TB>>>(pSumsq, D);
    colstat_k<<<448, D>>>(pY, N);
    bnfin_k<<<1, D>>>(gamma, beta, 1.0f / (float)N);
    bnapply4_k<<<cdiv(ND / 4, TB), TB>>>((float4*)pY, ND / 4);

    // ---- layer 2 ----
    spmm_k<<<sgrid, 256>>>(pY, pM, N);
    mma_gemm_k<<<ggrid, 256, GEMM_SMEM>>>(pM, W2, b2, nullptr, pX, N, D);
    zero_k<<<1, TB>>>(pSum, D);
    zero_k<<<1, TB>>>(pSumsq, D);
    colstat_k<<<448, D>>>(pX, N);
    bnfin_k<<<1, D>>>(gamma, beta, 1.0f / (float)N);
    bnapply4_k<<<cdiv(ND / 4, TB), TB>>>((float4*)pX, ND / 4);

    // ---- layer 3: gconv(X) -> out[0 : N*D] ----
    spmm_k<<<sgrid, 256>>>(pX, pM, N);
    mma_gemm_k<<<ggrid, 256, GEMM_SMEM>>>(pM, W3, b3, nullptr, out, N, D);

    // ---- head: logits = x @ W_lin + b_lin ----
    head_mma_k<<<hgrid, 256, HEAD_SMEM>>>(out, W_lin, b_lin, out + (size_t)N * D, N);
}

// round 6
// speedup vs baseline: 2.1826x; 1.1375x over previous
#include <cuda_runtime.h>
#include <cuda_fp16.h>
#include <cstdint>
#include <math.h>

#define D 256
#define F 1024
#define CLS 40
#define NMAX 50000
#define EMAX 300000

// ---------------- scratch (static device memory; no allocations) ----------------
__device__ float g_X[NMAX * D];
__device__ float g_Y[NMAX * D];
__device__ float g_M[NMAX * D];
__device__ float g_degout[NMAX];
__device__ float g_degin[NMAX];
__device__ float g_ns[NMAX];
__device__ float g_nd[NMAX];
__device__ float g_sum[D];
__device__ float g_sumsq[D];
__device__ float g_scale[D];
__device__ float g_shift[D];
// CSR by dst
__device__ int g_cnt[NMAX];
__device__ int g_rowptr[NMAX + 1];
__device__ int g_cursor[NMAX];
__device__ int g_esrc[EMAX];
__device__ int g_bsum[256];
__device__ int g_boff[256];

__device__ __forceinline__ uint32_t tf32r(float x) {
    uint32_t r;
    asm("cvt.rna.tf32.f32 %0, %1;" : "=r"(r) : "f"(x));
    return r;
}
__device__ __forceinline__ uint32_t h2pack(float lo, float hi) {
    __half2 h = __floats2half2_rn(lo, hi);
    return *(uint32_t*)&h;
}

// ---------------- fp16 mma.sync GEMM (Nc=256) ----------------
// C[M,256] = A[M,K] @ W[K,256] + bias, optional fused column sum/sumsq stats.
// CTA 128x128x32, 8 warps (2x4), warp 64x32, m16n8k16 fp16 HMMA, fp32 accum.
#define GEMM_SMEM 32768

__global__ __launch_bounds__(256, 2) void h_gemm_k(
    const float* __restrict__ A, const float* __restrict__ W,
    const float* __restrict__ bias, float* __restrict__ C,
    int M, int K, int doStats) {
    extern __shared__ uint32_t dsm[];
    uint32_t* sAb = dsm;         // [2][2048]
    uint32_t* sBb = dsm + 4096;  // [2][2048]

    const int tid = threadIdx.x;
    const int lane = tid & 31;
    const int wid = tid >> 5;
    const int wm = wid >> 2, wn = wid & 3;
    const int row0 = blockIdx.y * 128;
    const int col0 = blockIdx.x * 128;

    const int rbase = tid >> 3;         // A: rows 0..31 (+32j)
    const int c4 = (tid & 7) * 4;       // A: k offset 0..28

    float acc[4][4][4];
#pragma unroll
    for (int i = 0; i < 4; i++)
#pragma unroll
        for (int j = 0; j < 4; j++)
#pragma unroll
            for (int t = 0; t < 4; t++) acc[i][j][t] = 0.0f;

    const int nch = K >> 5;
    float4 av[4];
    float4 bv0[2], bv1[2];

    auto fetch = [&](int k0) {
#pragma unroll
        for (int j = 0; j < 4; j++) {
            int gr = row0 + rbase + 32 * j;
            av[j] = (gr < M) ? *(const float4*)(A + (size_t)gr * K + k0 + c4)
                             : make_float4(0.f, 0.f, 0.f, 0.f);
        }
#pragma unroll
        for (int jj = 0; jj < 2; jj++) {
            int item = tid + 256 * jj;
            int kp = item >> 5;              // 0..15 (k pair index)
            int n4 = (item & 31) * 4;        // 0..124
            bv0[jj] = *(const float4*)(W + (size_t)(k0 + 2 * kp) * 256 + col0 + n4);
            bv1[jj] = *(const float4*)(W + (size_t)(k0 + 2 * kp + 1) * 256 + col0 + n4);
        }
    };
    auto scat = [&](uint32_t* sa, uint32_t* sb) {
#pragma unroll
        for (int j = 0; j < 4; j++) {
            int r = rbase + 32 * j;
            int r16 = r & 15, mt = r >> 4;
            float vals[4] = {av[j].x, av[j].y, av[j].z, av[j].w};
#pragma unroll
            for (int p = 0; p < 2; p++) {
                int c = c4 + 2 * p;
                int c16 = c & 15, kt = c >> 4;
                int ln = (r16 & 7) * 4 + ((c16 >> 1) & 3);
                int rg = (r16 >> 3) + 2 * (c16 >> 3);
                sa[(kt * 8 + mt) * 128 + ln * 4 + rg] = h2pack(vals[2 * p], vals[2 * p + 1]);
            }
        }
#pragma unroll
        for (int jj = 0; jj < 2; jj++) {
            int item = tid + 256 * jj;
            int kp = item >> 5;
            int n4 = (item & 31) * 4;
            int kt = kp >> 3;
            int lnk = kp & 3;
            int rg = (kp & 7) >> 2;
            float v0[4] = {bv0[jj].x, bv0[jj].y, bv0[jj].z, bv0[jj].w};
            float v1[4] = {bv1[jj].x, bv1[jj].y, bv1[jj].z, bv1[jj].w};
#pragma unroll
            for (int t = 0; t < 4; t++) {
                int n = n4 + t;
                int n8 = n & 7, nt = n >> 3;
                sb[(kt * 16 + nt) * 64 + (n8 * 4 + lnk) * 2 + rg] = h2pack(v0[t], v1[t]);
            }
        }
    };

    fetch(0);
    scat(sAb, sBb);
    __syncthreads();

    for (int ch = 0; ch < nch; ch++) {
        const int s = ch & 1;
        if (ch + 1 < nch) fetch((ch + 1) << 5);

        const uint32_t* sa = sAb + s * 2048;
        const uint32_t* sb = sBb + s * 2048;
#pragma unroll
        for (int kk = 0; kk < 2; kk++) {
            uint32_t af[4][4];
            uint32_t bf[4][2];
#pragma unroll
            for (int im = 0; im < 4; im++) {
                uint4 u = *(const uint4*)(sa + (kk * 8 + wm * 4 + im) * 128 + lane * 4);
                af[im][0] = u.x; af[im][1] = u.y; af[im][2] = u.z; af[im][3] = u.w;
            }
#pragma unroll
            for (int in = 0; in < 4; in++) {
                uint2 u = *(const uint2*)(sb + (kk * 16 + wn * 4 + in) * 64 + lane * 2);
                bf[in][0] = u.x; bf[in][1] = u.y;
            }
#pragma unroll
            for (int im = 0; im < 4; im++)
#pragma unroll
                for (int in = 0; in < 4; in++)
                    asm volatile(
                        "mma.sync.aligned.m16n8k16.row.col.f32.f16.f16.f32 "
                        "{%0,%1,%2,%3}, {%4,%5,%6,%7}, {%8,%9}, {%0,%1,%2,%3};"
                        : "+f"(acc[im][in][0]), "+f"(acc[im][in][1]),
                          "+f"(acc[im][in][2]), "+f"(acc[im][in][3])
                        : "r"(af[im][0]), "r"(af[im][1]), "r"(af[im][2]), "r"(af[im][3]),
                          "r"(bf[in][0]), "r"(bf[in][1]));
        }
        if (ch + 1 < nch)
            scat(sAb + (s ^ 1) * 2048, sBb + (s ^ 1) * 2048);
        __syncthreads();
    }

    // epilogue: bias add, store, optional fused column stats
    float s_[4][2] = {{0.f}}, q_[4][2] = {{0.f}};
#pragma unroll
    for (int im = 0; im < 4; im++) {
        int rl = row0 + wm * 64 + im * 16 + (lane >> 2);
        int rh = rl + 8;
        bool vl = rl < M, vh = rh < M;
#pragma unroll
        for (int in = 0; in < 4; in++) {
            int cc = col0 + wn * 32 + in * 8 + (lane & 3) * 2;
            float b0 = bias[cc], b1 = bias[cc + 1];
            float v0 = acc[im][in][0] + b0, v1 = acc[im][in][1] + b1;
            float v2 = acc[im][in][2] + b0, v3 = acc[im][in][3] + b1;
            if (vl) {
                *(float2*)(C + (size_t)rl * 256 + cc) = make_float2(v0, v1);
                s_[in][0] += v0; q_[in][0] += v0 * v0;
                s_[in][1] += v1; q_[in][1] += v1 * v1;
            }
            if (vh) {
                *(float2*)(C + (size_t)rh * 256 + cc) = make_float2(v2, v3);
                s_[in][0] += v2; q_[in][0] += v2 * v2;
                s_[in][1] += v3; q_[in][1] += v3 * v3;
            }
        }
    }
    if (doStats) {
#pragma unroll
        for (int in = 0; in < 4; in++)
#pragma unroll
            for (int t = 0; t < 2; t++) {
#pragma unroll
                for (int m = 4; m < 32; m <<= 1) {
                    s_[in][t] += __shfl_xor_sync(0xFFFFFFFF, s_[in][t], m);
                    q_[in][t] += __shfl_xor_sync(0xFFFFFFFF, q_[in][t], m);
                }
            }
        if ((lane >> 2) == 0) {
#pragma unroll
            for (int in = 0; in < 4; in++)
#pragma unroll
                for (int t = 0; t < 2; t++) {
                    int cc = col0 + wn * 32 + in * 8 + (lane & 3) * 2 + t;
                    atomicAdd(&g_sum[cc], s_[in][t]);
                    atomicAdd(&g_sumsq[cc], q_[in][t]);
                }
        }
    }
}

// ---------------- tf32 mma head (K=256, Nc=40, padded to 64) ----------------
#define HEAD_SMEM 49152
__global__ __launch_bounds__(256, 2) void head_mma_k(
    const float* __restrict__ A, const float* __restrict__ W,
    const float* __restrict__ bias, float* __restrict__ C, int M) {
    extern __shared__ uint32_t hsm[];
    uint32_t* sAb = hsm;          // 2 x 4096
    uint32_t* sBb = hsm + 8192;   // 2 x 2048

    const int tid = threadIdx.x;
    const int lane = tid & 31;
    const int wid = tid >> 5;
    const int wm = wid >> 2, wn = wid & 3;
    const int row0 = blockIdx.y * 128;

    const int c4 = (tid & 7) * 4;
    const int rbase = tid >> 3;
    const int bn4 = (tid & 15) * 4;
    const int bkbase = tid >> 4;

    float acc[4][2][4];
#pragma unroll
    for (int i = 0; i < 4; i++)
#pragma unroll
        for (int j = 0; j < 2; j++)
#pragma unroll
            for (int t = 0; t < 4; t++) acc[i][j][t] = 0.0f;

    float4 av[4], bv[2];

    auto fetchH = [&](int k0) {
#pragma unroll
        for (int j = 0; j < 4; j++) {
            int gr = row0 + rbase + 32 * j;
            av[j] = (gr < M) ? *(const float4*)(A + (size_t)gr * 256 + k0 + c4)
                             : make_float4(0.f, 0.f, 0.f, 0.f);
        }
#pragma unroll
        for (int j = 0; j < 2; j++) {
            int k = bkbase + 16 * j;
            bv[j] = (bn4 < CLS) ? *(const float4*)(W + (size_t)(k0 + k) * CLS + bn4)
                                : make_float4(0.f, 0.f, 0.f, 0.f);
        }
    };
    auto scatH = [&](uint32_t* sa, uint32_t* sb) {
#pragma unroll
        for (int j = 0; j < 4; j++) {
            int r = rbase + 32 * j;
            int r16 = r & 15, mt = r >> 4;
            float vals[4] = {av[j].x, av[j].y, av[j].z, av[j].w};
#pragma unroll
            for (int t = 0; t < 4; t++) {
                int c = c4 + t;
                int kk = c >> 3, c8 = c & 7;
                int ln = (r16 & 7) * 4 + (c8 & 3);
                int sl = (r16 >> 3) | ((c8 >> 2) << 1);
                int tile = kk * 8 + mt;
                int lp = ln ^ ((tile >> 3) << 2);
                sa[(tile * 32 + lp) * 4 + sl] = tf32r(vals[t]);
            }
        }
#pragma unroll
        for (int j = 0; j < 2; j++) {
            int k = bkbase + 16 * j;
            int kk = k >> 3, k8 = k & 7;
            int sl = k8 >> 2, l4 = k8 & 3;
            float vals[4] = {bv[j].x, bv[j].y, bv[j].z, bv[j].w};
#pragma unroll
            for (int t = 0; t < 4; t++) {
                int n = bn4 + t;
                int nt = n >> 3, n8 = n & 7;
                int tile = kk * 8 + nt;
                int ln = n8 * 4 + l4;
                int lp = ln ^ ((tile & 7) << 2);
                sb[(tile * 32 + lp) * 2 + sl] = tf32r(vals[t]);
            }
        }
    };

    fetchH(0);
    scatH(sAb, sBb);
    __syncthreads();

#pragma unroll 1
    for (int ch = 0; ch < 8; ch++) {
        const int s = ch & 1;
        if (ch + 1 < 8) fetchH((ch + 1) << 5);
        const uint32_t* sa = sAb + s * 4096;
        const uint32_t* sb = sBb + s * 2048;
#pragma unroll
        for (int kk = 0; kk < 4; kk++) {
            uint32_t af[4][4];
            uint32_t bf[2][2];
#pragma unroll
            for (int im = 0; im < 4; im++) {
                int tile = kk * 8 + wm * 4 + im;
                int lp = lane ^ ((tile >> 3) << 2);
                uint4 u = *(const uint4*)(sa + (tile * 32 + lp) * 4);
                af[im][0] = u.x; af[im][1] = u.y; af[im][2] = u.z; af[im][3] = u.w;
            }
#pragma unroll
            for (int in = 0; in < 2; in++) {
                int tile = kk * 8 + wn * 2 + in;
                int lp = lane ^ ((tile & 7) << 2);
                uint2 u = *(const uint2*)(sb + (tile * 32 + lp) * 2);
                bf[in][0] = u.x; bf[in][1] = u.y;
            }
#pragma unroll
            for (int im = 0; im < 4; im++)
#pragma unroll
                for (int in = 0; in < 2; in++)
                    asm volatile(
                        "mma.sync.aligned.m16n8k8.row.col.f32.tf32.tf32.f32 "
                        "{%0,%1,%2,%3}, {%4,%5,%6,%7}, {%8,%9}, {%0,%1,%2,%3};"
                        : "+f"(acc[im][in][0]), "+f"(acc[im][in][1]),
                          "+f"(acc[im][in][2]), "+f"(acc[im][in][3])
                        : "r"(af[im][0]), "r"(af[im][1]), "r"(af[im][2]), "r"(af[im][3]),
                          "r"(bf[in][0]), "r"(bf[in][1]));
        }
        if (ch + 1 < 8) scatH(sAb + (s ^ 1) * 4096, sBb + (s ^ 1) * 2048);
        __syncthreads();
    }

#pragma unroll
    for (int im = 0; im < 4; im++) {
        int rl = row0 + wm * 64 + im * 16 + (lane >> 2);
        int rh = rl + 8;
#pragma unroll
        for (int in = 0; in < 2; in++) {
            int cc = wn * 16 + in * 8 + (lane & 3) * 2;
            if (cc >= CLS) continue;
            float b0 = bias[cc], b1 = bias[cc + 1];
            if (rl < M) {
                float2 v = make_float2(acc[im][in][0] + b0, acc[im][in][1] + b1);
                *(float2*)(C + (size_t)rl * CLS + cc) = v;
            }
            if (rh < M) {
                float2 v = make_float2(acc[im][in][2] + b0, acc[im][in][3] + b1);
                *(float2*)(C + (size_t)rh * CLS + cc) = v;
            }
        }
    }
}

// ---------------- CSR build ----------------
__global__ void zero_k(float* __restrict__ p, int n) {
    int i = blockIdx.x * blockDim.x + threadIdx.x;
    if (i < n) p[i] = 0.0f;
}
__global__ void zeroi_k(int* __restrict__ p, int n) {
    int i = blockIdx.x * blockDim.x + threadIdx.x;
    if (i < n) p[i] = 0;
}

__global__ void deg_k(const int* __restrict__ src, const int* __restrict__ dst, int E) {
    int e = blockIdx.x * blockDim.x + threadIdx.x;
    if (e < E) {
        atomicAdd(&g_degout[src[e]], 1.0f);
        atomicAdd(&g_degin[dst[e]], 1.0f);
        atomicAdd(&g_cnt[dst[e]], 1);
    }
}

__global__ void norm_k(int n) {
    int i = blockIdx.x * blockDim.x + threadIdx.x;
    if (i < n) {
        g_ns[i] = rsqrtf(fmaxf(g_degout[i], 1.0f));
        g_nd[i] = rsqrtf(fmaxf(g_degin[i], 1.0f));
    }
}

__global__ void scan1_k(int Nn) {
    __shared__ int sh[256];
    int i = blockIdx.x * 256 + threadIdx.x;
    int v = (i < Nn) ? g_cnt[i] : 0;
    sh[threadIdx.x] = v;
    __syncthreads();
    for (int off = 1; off < 256; off <<= 1) {
        int t = (threadIdx.x >= off) ? sh[threadIdx.x - off] : 0;
        __syncthreads();
        sh[threadIdx.x] += t;
        __syncthreads();
    }
    if (i < Nn) g_rowptr[i] = sh[threadIdx.x] - v;
    if (threadIdx.x == 255) g_bsum[blockIdx.x] = sh[255];
}

__global__ void scan2_k(int nb) {
    __shared__ int sh[256];
    int v = (threadIdx.x < nb) ? g_bsum[threadIdx.x] : 0;
    sh[threadIdx.x] = v;
    __syncthreads();
    for (int off = 1; off < 256; off <<= 1) {
        int t = (threadIdx.x >= off) ? sh[threadIdx.x - off] : 0;
        __syncthreads();
        sh[threadIdx.x] += t;
        __syncthreads();
    }
    g_boff[threadIdx.x] = sh[threadIdx.x] - v;
}

__global__ void scan3_k(int Nn, int E) {
    int i = blockIdx.x * 256 + threadIdx.x;
    if (i < Nn) {
        int r = g_rowptr[i] + g_boff[blockIdx.x];
        g_rowptr[i] = r;
        g_cursor[i] = r;
    }
    if (i == 0) g_rowptr[Nn] = E;
}

__global__ void fill_k(const int* __restrict__ src, const int* __restrict__ dst, int E) {
    int e = blockIdx.x * blockDim.x + threadIdx.x;
    if (e < E) {
        int pos = atomicAdd(&g_cursor[dst[e]], 1);
        g_esrc[pos] = src[e];
    }
}

// ---------------- CSR gather SpMM: Mo[n] = nd[n] * sum_{e: dst=n} ns[src]*X[src] ----
__global__ __launch_bounds__(256) void spmm_k(const float* __restrict__ X,
                                              float* __restrict__ Mo, int Nn) {
    int node = blockIdx.x * 4 + (threadIdx.x >> 6);
    if (node >= Nn) return;
    int t4 = (threadIdx.x & 63) << 2;
    int beg = g_rowptr[node], end = g_rowptr[node + 1];
    float4 a = make_float4(0.f, 0.f, 0.f, 0.f);
    for (int j = beg; j < end; j++) {
        int s = g_esrc[j];
        float sc = g_ns[s];
        float4 v = *(const float4*)(X + (size_t)s * D + t4);
        a.x += v.x * sc; a.y += v.y * sc; a.z += v.z * sc; a.w += v.w * sc;
    }
    float nd = g_nd[node];
    a.x *= nd; a.y *= nd; a.z *= nd; a.w *= nd;
    *(float4*)(Mo + (size_t)node * D + t4) = a;
}

// ---------------- batchnorm finalize + apply ----------------
__global__ void bnfin_k(const float* __restrict__ gamma, const float* __restrict__ beta,
                        float invN) {
    int c = threadIdx.x;
    float mean = g_sum[c] * invN;
    float var = g_sumsq[c] * invN - mean * mean;
    float sc = gamma[c] * rsqrtf(var + 1e-5f);
    g_scale[c] = sc;
    g_shift[c] = beta[c] - mean * sc;
}

__device__ __forceinline__ float elu1(float v) { return v > 0.0f ? v : expm1f(v); }

__global__ void bnapply4_k(float4* __restrict__ X, int n4) {
    int i = blockIdx.x * blockDim.x + threadIdx.x;
    if (i >= n4) return;
    int c = (i & 63) << 2;
    float4 v = X[i];
    v.x = elu1(v.x * g_scale[c + 0] + g_shift[c + 0]);
    v.y = elu1(v.y * g_scale[c + 1] + g_shift[c + 1]);
    v.z = elu1(v.z * g_scale[c + 2] + g_shift[c + 2]);
    v.w = elu1(v.w * g_scale[c + 3] + g_shift[c + 3]);
    X[i] = v;
}

// ---------------- host orchestration ----------------
static inline int cdiv(int a, int b) { return (a + b - 1) / b; }

extern "C" void kernel_launch(void* const* d_in, const int* in_sizes, int n_in,
                              void* d_out, int out_size) {
    const float* feat  = (const float*)d_in[0];
    const int*   src   = (const int*)d_in[1];
    const int*   dst   = (const int*)d_in[2];
    const float* W_fc  = (const float*)d_in[3];
    const float* b_fc  = (const float*)d_in[4];
    const float* W1    = (const float*)d_in[5];
    const float* b1    = (const float*)d_in[6];
    const float* W2    = (const float*)d_in[7];
    const float* b2    = (const float*)d_in[8];
    const float* W3    = (const float*)d_in[9];
    const float* b3    = (const float*)d_in[10];
    const float* gamma = (const float*)d_in[11];
    const float* beta  = (const float*)d_in[12];
    const float* W_lin = (const float*)d_in[13];
    const float* b_lin = (const float*)d_in[14];
    float* out = (float*)d_out;

    int N = in_sizes[0] / F;  // 50000
    int E = in_sizes[1];      // 300000

    cudaFuncSetAttribute(h_gemm_k, cudaFuncAttributeMaxDynamicSharedMemorySize, GEMM_SMEM);
    cudaFuncSetAttribute(head_mma_k, cudaFuncAttributeMaxDynamicSharedMemorySize, HEAD_SMEM);

    float *pX, *pY, *pM, *pDegO, *pDegI, *pSum, *pSumsq;
    int *pCnt;
    cudaGetSymbolAddress((void**)&pX, g_X);
    cudaGetSymbolAddress((void**)&pY, g_Y);
    cudaGetSymbolAddress((void**)&pM, g_M);
    cudaGetSymbolAddress((void**)&pDegO, g_degout);
    cudaGetSymbolAddress((void**)&pDegI, g_degin);
    cudaGetSymbolAddress((void**)&pSum, g_sum);
    cudaGetSymbolAddress((void**)&pSumsq, g_sumsq);
    cudaGetSymbolAddress((void**)&pCnt, g_cnt);

    const int ND = N * D;
    const int TB = 256;
    const int nb = cdiv(N, 256);
    const dim3 ggrid(2, cdiv(N, 128));
    const dim3 hgrid(1, cdiv(N, 128));
    const int sgrid = cdiv(N, 4);

    // ---- degree norms + CSR build ----
    zero_k<<<cdiv(N, TB), TB>>>(pDegO, N);
    zero_k<<<cdiv(N, TB), TB>>>(pDegI, N);
    zeroi_k<<<cdiv(N, TB), TB>>>(pCnt, N);
    deg_k<<<cdiv(E, TB), TB>>>(src, dst, E);
    norm_k<<<cdiv(N, TB), TB>>>(N);
    scan1_k<<<nb, 256>>>(N);
    scan2_k<<<1, 256>>>(nb);
    scan3_k<<<nb, 256>>>(N, E);
    fill_k<<<cdiv(E, TB), TB>>>(src, dst, E);

    // ---- FC: X = feat @ W_fc + b_fc ----
    h_gemm_k<<<ggrid, 256, GEMM_SMEM>>>(feat, W_fc, b_fc, pX, N, F, 0);

    // ---- layer 1 ----
    spmm_k<<<sgrid, 256>>>(pX, pM, N);
    zero_k<<<1, TB>>>(pSum, D);
    zero_k<<<1, TB>>>(pSumsq, D);
    h_gemm_k<<<ggrid, 256, GEMM_SMEM>>>(pM, W1, b1, pY, N, D, 1);
    bnfin_k<<<1, D>>>(gamma, beta, 1.0f / (float)N);
    bnapply4_k<<<cdiv(ND / 4, TB), TB>>>((float4*)pY, ND / 4);

    // ---- layer 2 ----
    spmm_k<<<sgrid, 256>>>(pY, pM, N);
    zero_k<<<1, TB>>>(pSum, D);
    zero_k<<<1, TB>>>(pSumsq, D);
    h_gemm_k<<<ggrid, 256, GEMM_SMEM>>>(pM, W2, b2, pX, N, D, 1);
    bnfin_k<<<1, D>>>(gamma, beta, 1.0f / (float)N);
    bnapply4_k<<<cdiv(ND / 4, TB), TB>>>((float4*)pX, ND / 4);

    // ---- layer 3: gconv(X) -> out[0 : N*D] ----
    spmm_k<<<sgrid, 256>>>(pX, pM, N);
    h_gemm_k<<<ggrid, 256, GEMM_SMEM>>>(pM, W3, b3, out, N, D, 0);

    // ---- head: logits = x @ W_lin + b_lin ----
    head_mma_k<<<hgrid, 256, HEAD_SMEM>>>(out, W_lin, b_lin, out + (size_t)N * D, N);
}

// round 7
// speedup vs baseline: 2.2052x; 1.0104x over previous
#include <cuda_runtime.h>
#include <cuda_fp16.h>
#include <cstdint>
#include <math.h>

#define D 256
#define F 1024
#define CLS 40
#define NMAX 50000
#define EMAX 300000

// ---------------- scratch (static device memory; no allocations) ----------------
__device__ __half g_Xh[NMAX * D];
__device__ __half g_Yh[NMAX * D];
__device__ __half g_Mh[NMAX * D];
__device__ float g_degout[NMAX];
__device__ float g_degin[NMAX];
__device__ float g_ns[NMAX];
__device__ float g_nd[NMAX];
__device__ float g_sum[D];
__device__ float g_sumsq[D];
__device__ float g_scale[D];
__device__ float g_shift[D];
// CSR by dst
__device__ int g_cnt[NMAX];
__device__ int g_rowptr[NMAX + 1];
__device__ int g_cursor[NMAX];
__device__ int g_esrc[EMAX];
__device__ int g_bsum[256];
__device__ int g_boff[256];

__device__ __forceinline__ uint32_t tf32r(float x) {
    uint32_t r;
    asm("cvt.rna.tf32.f32 %0, %1;" : "=r"(r) : "f"(x));
    return r;
}
__device__ __forceinline__ uint32_t h2pack(float lo, float hi) {
    __half2 h = __floats2half2_rn(lo, hi);
    return *(uint32_t*)&h;
}

// ---------------- fp16 mma.sync GEMM (Nc=256) ----------------
// C[M,256] = A[M,K] @ W[K,256] + bias; A fp32 or fp16; C fp32 or fp16;
// optional fused column sum/sumsq stats.
#define GEMM_SMEM 32768

template <int A_HALF, int C_HALF>
__global__ __launch_bounds__(256, 2) void h_gemm_t(
    const void* __restrict__ Av, const float* __restrict__ W,
    const float* __restrict__ bias, void* __restrict__ Cv,
    int M, int K, int doStats) {
    extern __shared__ uint32_t dsm[];
    uint32_t* sAb = dsm;         // [2][2048]
    uint32_t* sBb = dsm + 4096;  // [2][2048]

    const int tid = threadIdx.x;
    const int lane = tid & 31;
    const int wid = tid >> 5;
    const int wm = wid >> 2, wn = wid & 3;
    const int row0 = blockIdx.y * 128;
    const int col0 = blockIdx.x * 128;

    // fp32-A mapping
    const int rbase = tid >> 3;
    const int c4 = (tid & 7) * 4;
    // fp16-A mapping
    const int arow = tid >> 2;        // 0..63
    const int ak8 = (tid & 3) * 8;    // halves offset

    float acc[4][4][4];
#pragma unroll
    for (int i = 0; i < 4; i++)
#pragma unroll
        for (int j = 0; j < 4; j++)
#pragma unroll
            for (int t = 0; t < 4; t++) acc[i][j][t] = 0.0f;

    const int nch = K >> 5;
    float4 av[4];
    uint4 avh[2];
    float4 bv0[2], bv1[2];

    auto fetch = [&](int k0) {
        if (A_HALF) {
            const __half* Ah = (const __half*)Av;
#pragma unroll
            for (int j = 0; j < 2; j++) {
                int gr = row0 + arow + 64 * j;
                avh[j] = (gr < M) ? *(const uint4*)(Ah + (size_t)gr * K + k0 + ak8)
                                  : make_uint4(0, 0, 0, 0);
            }
        } else {
            const float* Af = (const float*)Av;
#pragma unroll
            for (int j = 0; j < 4; j++) {
                int gr = row0 + rbase + 32 * j;
                av[j] = (gr < M) ? *(const float4*)(Af + (size_t)gr * K + k0 + c4)
                                 : make_float4(0.f, 0.f, 0.f, 0.f);
            }
        }
#pragma unroll
        for (int jj = 0; jj < 2; jj++) {
            int item = tid + 256 * jj;
            int kp = item >> 5;
            int n4 = (item & 31) * 4;
            bv0[jj] = *(const float4*)(W + (size_t)(k0 + 2 * kp) * 256 + col0 + n4);
            bv1[jj] = *(const float4*)(W + (size_t)(k0 + 2 * kp + 1) * 256 + col0 + n4);
        }
    };
    auto scat = [&](uint32_t* sa, uint32_t* sb) {
        if (A_HALF) {
            const int q = tid & 3;
#pragma unroll
            for (int j = 0; j < 2; j++) {
                int r = arow + 64 * j;
                int r16 = r & 15, mt = r >> 4;
                uint32_t pr[4] = {avh[j].x, avh[j].y, avh[j].z, avh[j].w};
#pragma unroll
                for (int i = 0; i < 4; i++) {
                    int c2 = 4 * q + i;  // k-pair index 0..15
                    int kt = c2 >> 3;
                    int ln = (r16 & 7) * 4 + (c2 & 3);
                    int rg = (r16 >> 3) + 2 * ((c2 >> 2) & 1);
                    sa[(kt * 8 + mt) * 128 + ln * 4 + rg] = pr[i];
                }
            }
        } else {
#pragma unroll
            for (int j = 0; j < 4; j++) {
                int r = rbase + 32 * j;
                int r16 = r & 15, mt = r >> 4;
                float vals[4] = {av[j].x, av[j].y, av[j].z, av[j].w};
#pragma unroll
                for (int p = 0; p < 2; p++) {
                    int c = c4 + 2 * p;
                    int c16 = c & 15, kt = c >> 4;
                    int ln = (r16 & 7) * 4 + ((c16 >> 1) & 3);
                    int rg = (r16 >> 3) + 2 * (c16 >> 3);
                    sa[(kt * 8 + mt) * 128 + ln * 4 + rg] =
                        h2pack(vals[2 * p], vals[2 * p + 1]);
                }
            }
        }
#pragma unroll
        for (int jj = 0; jj < 2; jj++) {
            int item = tid + 256 * jj;
            int kp = item >> 5;
            int n4 = (item & 31) * 4;
            int kt = kp >> 3;
            int lnk = kp & 3;
            int rg = (kp & 7) >> 2;
            float v0[4] = {bv0[jj].x, bv0[jj].y, bv0[jj].z, bv0[jj].w};
            float v1[4] = {bv1[jj].x, bv1[jj].y, bv1[jj].z, bv1[jj].w};
#pragma unroll
            for (int t = 0; t < 4; t++) {
                int n = n4 + t;
                int n8 = n & 7, nt = n >> 3;
                sb[(kt * 16 + nt) * 64 + (n8 * 4 + lnk) * 2 + rg] = h2pack(v0[t], v1[t]);
            }
        }
    };

    fetch(0);
    scat(sAb, sBb);
    __syncthreads();

    for (int ch = 0; ch < nch; ch++) {
        const int s = ch & 1;
        if (ch + 1 < nch) fetch((ch + 1) << 5);

        const uint32_t* sa = sAb + s * 2048;
        const uint32_t* sb = sBb + s * 2048;
#pragma unroll
        for (int kk = 0; kk < 2; kk++) {
            uint32_t af[4][4];
            uint32_t bf[4][2];
#pragma unroll
            for (int im = 0; im < 4; im++) {
                uint4 u = *(const uint4*)(sa + (kk * 8 + wm * 4 + im) * 128 + lane * 4);
                af[im][0] = u.x; af[im][1] = u.y; af[im][2] = u.z; af[im][3] = u.w;
            }
#pragma unroll
            for (int in = 0; in < 4; in++) {
                uint2 u = *(const uint2*)(sb + (kk * 16 + wn * 4 + in) * 64 + lane * 2);
                bf[in][0] = u.x; bf[in][1] = u.y;
            }
#pragma unroll
            for (int im = 0; im < 4; im++)
#pragma unroll
                for (int in = 0; in < 4; in++)
                    asm volatile(
                        "mma.sync.aligned.m16n8k16.row.col.f32.f16.f16.f32 "
                        "{%0,%1,%2,%3}, {%4,%5,%6,%7}, {%8,%9}, {%0,%1,%2,%3};"
                        : "+f"(acc[im][in][0]), "+f"(acc[im][in][1]),
                          "+f"(acc[im][in][2]), "+f"(acc[im][in][3])
                        : "r"(af[im][0]), "r"(af[im][1]), "r"(af[im][2]), "r"(af[im][3]),
                          "r"(bf[in][0]), "r"(bf[in][1]));
        }
        if (ch + 1 < nch)
            scat(sAb + (s ^ 1) * 2048, sBb + (s ^ 1) * 2048);
        __syncthreads();
    }

    // epilogue
    float s_[4][2] = {{0.f}}, q_[4][2] = {{0.f}};
#pragma unroll
    for (int im = 0; im < 4; im++) {
        int rl = row0 + wm * 64 + im * 16 + (lane >> 2);
        int rh = rl + 8;
        bool vl = rl < M, vh = rh < M;
#pragma unroll
        for (int in = 0; in < 4; in++) {
            int cc = col0 + wn * 32 + in * 8 + (lane & 3) * 2;
            float b0 = bias[cc], b1 = bias[cc + 1];
            float v0 = acc[im][in][0] + b0, v1 = acc[im][in][1] + b1;
            float v2 = acc[im][in][2] + b0, v3 = acc[im][in][3] + b1;
            if (vl) {
                if (C_HALF)
                    *(__half2*)((__half*)Cv + (size_t)rl * 256 + cc) = __floats2half2_rn(v0, v1);
                else
                    *(float2*)((float*)Cv + (size_t)rl * 256 + cc) = make_float2(v0, v1);
                s_[in][0] += v0; q_[in][0] += v0 * v0;
                s_[in][1] += v1; q_[in][1] += v1 * v1;
            }
            if (vh) {
                if (C_HALF)
                    *(__half2*)((__half*)Cv + (size_t)rh * 256 + cc) = __floats2half2_rn(v2, v3);
                else
                    *(float2*)((float*)Cv + (size_t)rh * 256 + cc) = make_float2(v2, v3);
                s_[in][0] += v2; q_[in][0] += v2 * v2;
                s_[in][1] += v3; q_[in][1] += v3 * v3;
            }
        }
    }
    if (doStats) {
#pragma unroll
        for (int in = 0; in < 4; in++)
#pragma unroll
            for (int t = 0; t < 2; t++) {
#pragma unroll
                for (int m = 4; m < 32; m <<= 1) {
                    s_[in][t] += __shfl_xor_sync(0xFFFFFFFF, s_[in][t], m);
                    q_[in][t] += __shfl_xor_sync(0xFFFFFFFF, q_[in][t], m);
                }
            }
        if ((lane >> 2) == 0) {
#pragma unroll
            for (int in = 0; in < 4; in++)
#pragma unroll
                for (int t = 0; t < 2; t++) {
                    int cc = col0 + wn * 32 + in * 8 + (lane & 3) * 2 + t;
                    atomicAdd(&g_sum[cc], s_[in][t]);
                    atomicAdd(&g_sumsq[cc], q_[in][t]);
                }
        }
    }
}

// ---------------- tf32 mma head (K=256, Nc=40, padded to 64) ----------------
#define HEAD_SMEM 49152
__global__ __launch_bounds__(256, 2) void head_mma_k(
    const float* __restrict__ A, const float* __restrict__ W,
    const float* __restrict__ bias, float* __restrict__ C, int M) {
    extern __shared__ uint32_t hsm[];
    uint32_t* sAb = hsm;
    uint32_t* sBb = hsm + 8192;

    const int tid = threadIdx.x;
    const int lane = tid & 31;
    const int wid = tid >> 5;
    const int wm = wid >> 2, wn = wid & 3;
    const int row0 = blockIdx.y * 128;

    const int c4 = (tid & 7) * 4;
    const int rbase = tid >> 3;
    const int bn4 = (tid & 15) * 4;
    const int bkbase = tid >> 4;

    float acc[4][2][4];
#pragma unroll
    for (int i = 0; i < 4; i++)
#pragma unroll
        for (int j = 0; j < 2; j++)
#pragma unroll
            for (int t = 0; t < 4; t++) acc[i][j][t] = 0.0f;

    float4 av[4], bv[2];

    auto fetchH = [&](int k0) {
#pragma unroll
        for (int j = 0; j < 4; j++) {
            int gr = row0 + rbase + 32 * j;
            av[j] = (gr < M) ? *(const float4*)(A + (size_t)gr * 256 + k0 + c4)
                             : make_float4(0.f, 0.f, 0.f, 0.f);
        }
#pragma unroll
        for (int j = 0; j < 2; j++) {
            int k = bkbase + 16 * j;
            bv[j] = (bn4 < CLS) ? *(const float4*)(W + (size_t)(k0 + k) * CLS + bn4)
                                : make_float4(0.f, 0.f, 0.f, 0.f);
        }
    };
    auto scatH = [&](uint32_t* sa, uint32_t* sb) {
#pragma unroll
        for (int j = 0; j < 4; j++) {
            int r = rbase + 32 * j;
            int r16 = r & 15, mt = r >> 4;
            float vals[4] = {av[j].x, av[j].y, av[j].z, av[j].w};
#pragma unroll
            for (int t = 0; t < 4; t++) {
                int c = c4 + t;
                int kk = c >> 3, c8 = c & 7;
                int ln = (r16 & 7) * 4 + (c8 & 3);
                int sl = (r16 >> 3) | ((c8 >> 2) << 1);
                int tile = kk * 8 + mt;
                int lp = ln ^ ((tile >> 3) << 2);
                sa[(tile * 32 + lp) * 4 + sl] = tf32r(vals[t]);
            }
        }
#pragma unroll
        for (int j = 0; j < 2; j++) {
            int k = bkbase + 16 * j;
            int kk = k >> 3, k8 = k & 7;
            int sl = k8 >> 2, l4 = k8 & 3;
            float vals[4] = {bv[j].x, bv[j].y, bv[j].z, bv[j].w};
#pragma unroll
            for (int t = 0; t < 4; t++) {
                int n = bn4 + t;
                int nt = n >> 3, n8 = n & 7;
                int tile = kk * 8 + nt;
                int ln = n8 * 4 + l4;
                int lp = ln ^ ((tile & 7) << 2);
                sb[(tile * 32 + lp) * 2 + sl] = tf32r(vals[t]);
            }
        }
    };

    fetchH(0);
    scatH(sAb, sBb);
    __syncthreads();

#pragma unroll 1
    for (int ch = 0; ch < 8; ch++) {
        const int s = ch & 1;
        if (ch + 1 < 8) fetchH((ch + 1) << 5);
        const uint32_t* sa = sAb + s * 4096;
        const uint32_t* sb = sBb + s * 2048;
#pragma unroll
        for (int kk = 0; kk < 4; kk++) {
            uint32_t af[4][4];
            uint32_t bf[2][2];
#pragma unroll
            for (int im = 0; im < 4; im++) {
                int tile = kk * 8 + wm * 4 + im;
                int lp = lane ^ ((tile >> 3) << 2);
                uint4 u = *(const uint4*)(sa + (tile * 32 + lp) * 4);
                af[im][0] = u.x; af[im][1] = u.y; af[im][2] = u.z; af[im][3] = u.w;
            }
#pragma unroll
            for (int in = 0; in < 2; in++) {
                int tile = kk * 8 + wn * 2 + in;
                int lp = lane ^ ((tile & 7) << 2);
                uint2 u = *(const uint2*)(sb + (tile * 32 + lp) * 2);
                bf[in][0] = u.x; bf[in][1] = u.y;
            }
#pragma unroll
            for (int im = 0; im < 4; im++)
#pragma unroll
                for (int in = 0; in < 2; in++)
                    asm volatile(
                        "mma.sync.aligned.m16n8k8.row.col.f32.tf32.tf32.f32 "
                        "{%0,%1,%2,%3}, {%4,%5,%6,%7}, {%8,%9}, {%0,%1,%2,%3};"
                        : "+f"(acc[im][in][0]), "+f"(acc[im][in][1]),
                          "+f"(acc[im][in][2]), "+f"(acc[im][in][3])
                        : "r"(af[im][0]), "r"(af[im][1]), "r"(af[im][2]), "r"(af[im][3]),
                          "r"(bf[in][0]), "r"(bf[in][1]));
        }
        if (ch + 1 < 8) scatH(sAb + (s ^ 1) * 4096, sBb + (s ^ 1) * 2048);
        __syncthreads();
    }

#pragma unroll
    for (int im = 0; im < 4; im++) {
        int rl = row0 + wm * 64 + im * 16 + (lane >> 2);
        int rh = rl + 8;
#pragma unroll
        for (int in = 0; in < 2; in++) {
            int cc = wn * 16 + in * 8 + (lane & 3) * 2;
            if (cc >= CLS) continue;
            float b0 = bias[cc], b1 = bias[cc + 1];
            if (rl < M) {
                float2 v = make_float2(acc[im][in][0] + b0, acc[im][in][1] + b1);
                *(float2*)(C + (size_t)rl * CLS + cc) = v;
            }
            if (rh < M) {
                float2 v = make_float2(acc[im][in][2] + b0, acc[im][in][3] + b1);
                *(float2*)(C + (size_t)rh * CLS + cc) = v;
            }
        }
    }
}

// ---------------- CSR build ----------------
__global__ void zero_k(float* __restrict__ p, int n) {
    int i = blockIdx.x * blockDim.x + threadIdx.x;
    if (i < n) p[i] = 0.0f;
}
__global__ void zeroi_k(int* __restrict__ p, int n) {
    int i = blockIdx.x * blockDim.x + threadIdx.x;
    if (i < n) p[i] = 0;
}
__global__ void zstats_k() {
    int i = threadIdx.x;  // <<<1, D>>>
    g_sum[i] = 0.0f;
    g_sumsq[i] = 0.0f;
}

__global__ void deg_k(const int* __restrict__ src, const int* __restrict__ dst, int E) {
    int e = blockIdx.x * blockDim.x + threadIdx.x;
    if (e < E) {
        atomicAdd(&g_degout[src[e]], 1.0f);
        atomicAdd(&g_degin[dst[e]], 1.0f);
        atomicAdd(&g_cnt[dst[e]], 1);
    }
}

__global__ void norm_k(int n) {
    int i = blockIdx.x * blockDim.x + threadIdx.x;
    if (i < n) {
        g_ns[i] = rsqrtf(fmaxf(g_degout[i], 1.0f));
        g_nd[i] = rsqrtf(fmaxf(g_degin[i], 1.0f));
    }
}

__global__ void scan1_k(int Nn) {
    __shared__ int sh[256];
    int i = blockIdx.x * 256 + threadIdx.x;
    int v = (i < Nn) ? g_cnt[i] : 0;
    sh[threadIdx.x] = v;
    __syncthreads();
    for (int off = 1; off < 256; off <<= 1) {
        int t = (threadIdx.x >= off) ? sh[threadIdx.x - off] : 0;
        __syncthreads();
        sh[threadIdx.x] += t;
        __syncthreads();
    }
    if (i < Nn) g_rowptr[i] = sh[threadIdx.x] - v;
    if (threadIdx.x == 255) g_bsum[blockIdx.x] = sh[255];
}

__global__ void scan2_k(int nb) {
    __shared__ int sh[256];
    int v = (threadIdx.x < nb) ? g_bsum[threadIdx.x] : 0;
    sh[threadIdx.x] = v;
    __syncthreads();
    for (int off = 1; off < 256; off <<= 1) {
        int t = (threadIdx.x >= off) ? sh[threadIdx.x - off] : 0;
        __syncthreads();
        sh[threadIdx.x] += t;
        __syncthreads();
    }
    g_boff[threadIdx.x] = sh[threadIdx.x] - v;
}

__global__ void scan3_k(int Nn, int E) {
    int i = blockIdx.x * 256 + threadIdx.x;
    if (i < Nn) {
        int r = g_rowptr[i] + g_boff[blockIdx.x];
        g_rowptr[i] = r;
        g_cursor[i] = r;
    }
    if (i == 0) g_rowptr[Nn] = E;
}

__global__ void fill_k(const int* __restrict__ src, const int* __restrict__ dst, int E) {
    int e = blockIdx.x * blockDim.x + threadIdx.x;
    if (e < E) {
        int pos = atomicAdd(&g_cursor[dst[e]], 1);
        g_esrc[pos] = src[e];
    }
}

// ---------------- CSR gather SpMM (fp16 in/out, fp32 accum) ----------------
__global__ __launch_bounds__(256) void spmmh_k(const __half* __restrict__ X,
                                               __half* __restrict__ Mo, int Nn) {
    int node = blockIdx.x * 4 + (threadIdx.x >> 6);
    if (node >= Nn) return;
    int c0 = (threadIdx.x & 63) * 4;
    int beg = g_rowptr[node], end = g_rowptr[node + 1];
    float a0 = 0.f, a1 = 0.f, a2 = 0.f, a3 = 0.f;
    for (int j = beg; j < end; j++) {
        int s = g_esrc[j];
        float sc = g_ns[s];
        uint2 u = *(const uint2*)(X + (size_t)s * D + c0);
        float2 f0 = __half22float2(*(__half2*)&u.x);
        float2 f1 = __half22float2(*(__half2*)&u.y);
        a0 += f0.x * sc; a1 += f0.y * sc; a2 += f1.x * sc; a3 += f1.y * sc;
    }
    float nd = g_nd[node];
    __half2 o0 = __floats2half2_rn(a0 * nd, a1 * nd);
    __half2 o1 = __floats2half2_rn(a2 * nd, a3 * nd);
    uint2 o;
    o.x = *(uint32_t*)&o0;
    o.y = *(uint32_t*)&o1;
    *(uint2*)(Mo + (size_t)node * D + c0) = o;
}

// ---------------- batchnorm finalize + apply (fp16) ----------------
__global__ void bnfin_k(const float* __restrict__ gamma, const float* __restrict__ beta,
                        float invN) {
    int c = threadIdx.x;
    float mean = g_sum[c] * invN;
    float var = g_sumsq[c] * invN - mean * mean;
    float sc = gamma[c] * rsqrtf(var + 1e-5f);
    g_scale[c] = sc;
    g_shift[c] = beta[c] - mean * sc;
}

__device__ __forceinline__ float elu1(float v) { return v > 0.0f ? v : expm1f(v); }

__global__ void bnapplyh_k(uint4* __restrict__ X, int n8) {
    int i = blockIdx.x * blockDim.x + threadIdx.x;
    if (i >= n8) return;
    int c = (i & 31) * 8;
    uint4 u = X[i];
    __half2* h = (__half2*)&u;
#pragma unroll
    for (int t = 0; t < 4; t++) {
        float2 f = __half22float2(h[t]);
        f.x = elu1(f.x * g_scale[c + 2 * t] + g_shift[c + 2 * t]);
        f.y = elu1(f.y * g_scale[c + 2 * t + 1] + g_shift[c + 2 * t + 1]);
        h[t] = __floats2half2_rn(f.x, f.y);
    }
    X[i] = u;
}

// ---------------- host orchestration ----------------
static inline int cdiv(int a, int b) { return (a + b - 1) / b; }

extern "C" void kernel_launch(void* const* d_in, const int* in_sizes, int n_in,
                              void* d_out, int out_size) {
    const float* feat  = (const float*)d_in[0];
    const int*   src   = (const int*)d_in[1];
    const int*   dst   = (const int*)d_in[2];
    const float* W_fc  = (const float*)d_in[3];
    const float* b_fc  = (const float*)d_in[4];
    const float* W1    = (const float*)d_in[5];
    const float* b1    = (const float*)d_in[6];
    const float* W2    = (const float*)d_in[7];
    const float* b2    = (const float*)d_in[8];
    const float* W3    = (const float*)d_in[9];
    const float* b3    = (const float*)d_in[10];
    const float* gamma = (const float*)d_in[11];
    const float* beta  = (const float*)d_in[12];
    const float* W_lin = (const float*)d_in[13];
    const float* b_lin = (const float*)d_in[14];
    float* out = (float*)d_out;

    int N = in_sizes[0] / F;  // 50000
    int E = in_sizes[1];      // 300000

    cudaFuncSetAttribute(h_gemm_t<0, 1>, cudaFuncAttributeMaxDynamicSharedMemorySize, GEMM_SMEM);
    cudaFuncSetAttribute(h_gemm_t<1, 1>, cudaFuncAttributeMaxDynamicSharedMemorySize, GEMM_SMEM);
    cudaFuncSetAttribute(h_gemm_t<1, 0>, cudaFuncAttributeMaxDynamicSharedMemorySize, GEMM_SMEM);
    cudaFuncSetAttribute(head_mma_k, cudaFuncAttributeMaxDynamicSharedMemorySize, HEAD_SMEM);

    __half *pXh, *pYh, *pMh;
    float *pDegO, *pDegI;
    int *pCnt;
    cudaGetSymbolAddress((void**)&pXh, g_Xh);
    cudaGetSymbolAddress((void**)&pYh, g_Yh);
    cudaGetSymbolAddress((void**)&pMh, g_Mh);
    cudaGetSymbolAddress((void**)&pDegO, g_degout);
    cudaGetSymbolAddress((void**)&pDegI, g_degin);
    cudaGetSymbolAddress((void**)&pCnt, g_cnt);

    const int ND = N * D;
    const int TB = 256;
    const int nb = cdiv(N, 256);
    const dim3 ggrid(2, cdiv(N, 128));
    const dim3 hgrid(1, cdiv(N, 128));
    const int sgrid = cdiv(N, 4);

    // ---- degree norms + CSR build ----
    zero_k<<<cdiv(N, TB), TB>>>(pDegO, N);
    zero_k<<<cdiv(N, TB), TB>>>(pDegI, N);
    zeroi_k<<<cdiv(N, TB), TB>>>(pCnt, N);
    deg_k<<<cdiv(E, TB), TB>>>(src, dst, E);
    norm_k<<<cdiv(N, TB), TB>>>(N);
    scan1_k<<<nb, 256>>>(N);
    scan2_k<<<1, 256>>>(nb);
    scan3_k<<<nb, 256>>>(N, E);
    fill_k<<<cdiv(E, TB), TB>>>(src, dst, E);

    // ---- FC: Xh = feat @ W_fc + b_fc (fp32 in, fp16 out) ----
    h_gemm_t<0, 1><<<ggrid, 256, GEMM_SMEM>>>(feat, W_fc, b_fc, pXh, N, F, 0);

    // ---- layer 1 ----
    spmmh_k<<<sgrid, 256>>>(pXh, pMh, N);
    zstats_k<<<1, D>>>();
    h_gemm_t<1, 1><<<ggrid, 256, GEMM_SMEM>>>(pMh, W1, b1, pYh, N, D, 1);
    bnfin_k<<<1, D>>>(gamma, beta, 1.0f / (float)N);
    bnapplyh_k<<<cdiv(ND / 8, TB), TB>>>((uint4*)pYh, ND / 8);

    // ---- layer 2 ----
    spmmh_k<<<sgrid, 256>>>(pYh, pMh, N);
    zstats_k<<<1, D>>>();
    h_gemm_t<1, 1><<<ggrid, 256, GEMM_SMEM>>>(pMh, W2, b2, pXh, N, D, 1);
    bnfin_k<<<1, D>>>(gamma, beta, 1.0f / (float)N);
    bnapplyh_k<<<cdiv(ND / 8, TB), TB>>>((uint4*)pXh, ND / 8);

    // ---- layer 3: gconv -> out[0 : N*D] fp32 ----
    spmmh_k<<<sgrid, 256>>>(pXh, pMh, N);
    h_gemm_t<1, 0><<<ggrid, 256, GEMM_SMEM>>>(pMh, W3, b3, out, N, D, 0);

    // ---- head: logits = x @ W_lin + b_lin ----
    head_mma_k<<<hgrid, 256, HEAD_SMEM>>>(out, W_lin, b_lin, out + (size_t)N * D, N);
}

// round 11
// speedup vs baseline: 4.0263x; 1.8258x over previous
#include <cuda_runtime.h>
#include <cuda_fp16.h>
#include <cstdint>
#include <math.h>

#define D 256
#define F 1024
#define CLS 40
#define NMAX 50000
#define EMAX 300000
#define ROWW 20  // padded words per 32-half tile row (bank-conflict-free bijection)

// ---------------- scratch (static device memory; no allocations) ----------------
__device__ __half g_Xh[NMAX * D];
__device__ __half g_Yh[NMAX * D];
__device__ __half g_Mh[NMAX * D];
__device__ __half g_Wth[256 * 1024];  // transposed fp16 weights [n][k], reused per layer
__device__ float g_degout[NMAX];
__device__ float g_degin[NMAX];
__device__ float g_ns[NMAX];
__device__ float g_nd[NMAX];
__device__ float g_sum[D];
__device__ float g_sumsq[D];
__device__ float g_scale[D];
__device__ float g_shift[D];
// CSR by dst
__device__ int g_cnt[NMAX];
__device__ int g_rowptr[NMAX + 1];
__device__ int g_cursor[NMAX];
__device__ int g_esrc[EMAX];
__device__ int g_bsum[256];
__device__ int g_boff[256];

__device__ __forceinline__ uint32_t tf32r(float x) {
    uint32_t r;
    asm("cvt.rna.tf32.f32 %0, %1;" : "=r"(r) : "f"(x));
    return r;
}
__device__ __forceinline__ uint32_t h2pack(float lo, float hi) {
    __half2 h = __floats2half2_rn(lo, hi);
    return *(uint32_t*)&h;
}

// ---------------- weight transpose+convert: W[K][256] fp32 -> Wt[256][K] fp16 ----
__global__ void wt_k(const float* __restrict__ W, __half* __restrict__ Wt, int K) {
    __shared__ float t[32][33];
    int k0 = blockIdx.x * 32, n0 = blockIdx.y * 32;
    int x = threadIdx.x, y = threadIdx.y;  // 32 x 8
    for (int j = y; j < 32; j += 8) t[j][x] = W[(size_t)(k0 + j) * 256 + n0 + x];
    __syncthreads();
    for (int j = y; j < 32; j += 8)
        Wt[(size_t)(n0 + j) * K + k0 + x] = __float2half(t[x][j]);
}

// ---------------- fp16 mma.sync GEMM (Nc=256) ----------------
// C[M,256] = A[M,K] @ Wt^T + bias; Wt is [256][K] fp16 (n-major).
// CTA 128x128x32, 8 warps (2x4), warp 64x32, m16n8k16, fp32 accum.
// smem: A,B tiles row-major [128][32] halves, rows padded to ROWW words.
#define TILE_WORDS (128 * ROWW)          // 2560 words per buffer
#define GEMM_SMEM (4 * TILE_WORDS * 4)   // 2 bufs x (A+B) = 40960 B

template <int A_HALF, int C_HALF>
__global__ __launch_bounds__(256, 2) void h_gemm_t(
    const void* __restrict__ Av, const __half* __restrict__ Wt,
    const float* __restrict__ bias, void* __restrict__ Cv,
    int M, int K, int doStats) {
    extern __shared__ uint32_t dsm[];
    // [buf0: A, B][buf1: A, B]
    const int tid = threadIdx.x;
    const int lane = tid & 31;
    const int wid = tid >> 5;
    const int wm = wid >> 2, wn = wid & 3;
    const int row0 = blockIdx.y * 128;
    const int col0 = blockIdx.x * 128;

    const int srow = tid >> 2;     // 0..63 (row handled, +64 for jj=1)
    const int sq = tid & 3;        // 8-half segment within row

    float acc[4][4][4];
#pragma unroll
    for (int i = 0; i < 4; i++)
#pragma unroll
        for (int j = 0; j < 4; j++)
#pragma unroll
            for (int t = 0; t < 4; t++) acc[i][j][t] = 0.0f;

    const int nch = K >> 5;
    uint4 ar[2];   // A stage regs (fp16 form) or converted below
    float4 af32[2][2];
    uint4 br[2];

    auto fetch = [&](int k0) {
#pragma unroll
        for (int jj = 0; jj < 2; jj++) {
            int m = srow + 64 * jj;
            int gr = row0 + m;
            if (A_HALF) {
                const __half* Ah = (const __half*)Av;
                ar[jj] = (gr < M) ? *(const uint4*)(Ah + (size_t)gr * K + k0 + 8 * sq)
                                  : make_uint4(0, 0, 0, 0);
            } else {
                const float* Af = (const float*)Av;
                if (gr < M) {
                    af32[jj][0] = *(const float4*)(Af + (size_t)gr * K + k0 + 8 * sq);
                    af32[jj][1] = *(const float4*)(Af + (size_t)gr * K + k0 + 8 * sq + 4);
                } else {
                    af32[jj][0] = make_float4(0.f, 0.f, 0.f, 0.f);
                    af32[jj][1] = make_float4(0.f, 0.f, 0.f, 0.f);
                }
            }
            int n = srow + 64 * jj;
            br[jj] = *(const uint4*)(Wt + (size_t)(col0 + n) * K + k0 + 8 * sq);
        }
    };
    auto scat = [&](uint32_t* sA, uint32_t* sB) {
#pragma unroll
        for (int jj = 0; jj < 2; jj++) {
            int r = srow + 64 * jj;
            uint4 a;
            if (A_HALF) {
                a = ar[jj];
            } else {
                a.x = h2pack(af32[jj][0].x, af32[jj][0].y);
                a.y = h2pack(af32[jj][0].z, af32[jj][0].w);
                a.z = h2pack(af32[jj][1].x, af32[jj][1].y);
                a.w = h2pack(af32[jj][1].z, af32[jj][1].w);
            }
            *(uint4*)(sA + r * ROWW + 4 * sq) = a;
            *(uint4*)(sB + r * ROWW + 4 * sq) = br[jj];
        }
    };

    fetch(0);
    scat(dsm, dsm + TILE_WORDS);
    __syncthreads();

    for (int ch = 0; ch < nch; ch++) {
        const int s = ch & 1;
        if (ch + 1 < nch) fetch((ch + 1) << 5);

        const uint32_t* sA = dsm + s * 2 * TILE_WORDS;
        const uint32_t* sB = sA + TILE_WORDS;
        const int lq = lane & 3;
        const int lr = lane >> 2;
#pragma unroll
        for (int kk = 0; kk < 2; kk++) {
            uint32_t afr[4][4];
            uint32_t bfr[4][2];
#pragma unroll
            for (int im = 0; im < 4; im++) {
                int m = wm * 64 + im * 16 + lr;
                const uint32_t* p0 = sA + m * ROWW + kk * 8 + lq;
                const uint32_t* p1 = sA + (m + 8) * ROWW + kk * 8 + lq;
                afr[im][0] = p0[0];
                afr[im][1] = p1[0];
                afr[im][2] = p0[4];
                afr[im][3] = p1[4];
            }
#pragma unroll
            for (int in = 0; in < 4; in++) {
                int n = wn * 32 + in * 8 + lr;
                const uint32_t* p = sB + n * ROWW + kk * 8 + lq;
                bfr[in][0] = p[0];
                bfr[in][1] = p[4];
            }
#pragma unroll
            for (int im = 0; im < 4; im++)
#pragma unroll
                for (int in = 0; in < 4; in++)
                    asm volatile(
                        "mma.sync.aligned.m16n8k16.row.col.f32.f16.f16.f32 "
                        "{%0,%1,%2,%3}, {%4,%5,%6,%7}, {%8,%9}, {%0,%1,%2,%3};"
                        : "+f"(acc[im][in][0]), "+f"(acc[im][in][1]),
                          "+f"(acc[im][in][2]), "+f"(acc[im][in][3])
                        : "r"(afr[im][0]), "r"(afr[im][1]), "r"(afr[im][2]), "r"(afr[im][3]),
                          "r"(bfr[in][0]), "r"(bfr[in][1]));
        }
        if (ch + 1 < nch) {
            uint32_t* nA = dsm + (s ^ 1) * 2 * TILE_WORDS;
            scat(nA, nA + TILE_WORDS);
        }
        __syncthreads();
    }

    // epilogue
    float s_[4][2] = {{0.f}}, q_[4][2] = {{0.f}};
#pragma unroll
    for (int im = 0; im < 4; im++) {
        int rl = row0 + wm * 64 + im * 16 + (lane >> 2);
        int rh = rl + 8;
        bool vl = rl < M, vh = rh < M;
#pragma unroll
        for (int in = 0; in < 4; in++) {
            int cc = col0 + wn * 32 + in * 8 + (lane & 3) * 2;
            float b0 = bias[cc], b1 = bias[cc + 1];
            float v0 = acc[im][in][0] + b0, v1 = acc[im][in][1] + b1;
            float v2 = acc[im][in][2] + b0, v3 = acc[im][in][3] + b1;
            if (vl) {
                if (C_HALF)
                    *(__half2*)((__half*)Cv + (size_t)rl * 256 + cc) = __floats2half2_rn(v0, v1);
                else
                    *(float2*)((float*)Cv + (size_t)rl * 256 + cc) = make_float2(v0, v1);
                s_[in][0] += v0; q_[in][0] += v0 * v0;
                s_[in][1] += v1; q_[in][1] += v1 * v1;
            }
            if (vh) {
                if (C_HALF)
                    *(__half2*)((__half*)Cv + (size_t)rh * 256 + cc) = __floats2half2_rn(v2, v3);
                else
                    *(float2*)((float*)Cv + (size_t)rh * 256 + cc) = make_float2(v2, v3);
                s_[in][0] += v2; q_[in][0] += v2 * v2;
                s_[in][1] += v3; q_[in][1] += v3 * v3;
            }
        }
    }
    if (doStats) {
#pragma unroll
        for (int in = 0; in < 4; in++)
#pragma unroll
            for (int t = 0; t < 2; t++) {
#pragma unroll
                for (int m = 4; m < 32; m <<= 1) {
                    s_[in][t] += __shfl_xor_sync(0xFFFFFFFF, s_[in][t], m);
                    q_[in][t] += __shfl_xor_sync(0xFFFFFFFF, q_[in][t], m);
                }
            }
        if ((lane >> 2) == 0) {
#pragma unroll
            for (int in = 0; in < 4; in++)
#pragma unroll
                for (int t = 0; t < 2; t++) {
                    int cc = col0 + wn * 32 + in * 8 + (lane & 3) * 2 + t;
                    atomicAdd(&g_sum[cc], s_[in][t]);
                    atomicAdd(&g_sumsq[cc], q_[in][t]);
                }
        }
    }
}

// ---------------- tf32 mma head (K=256, Nc=40, padded to 64) ----------------
#define HEAD_SMEM 49152
__global__ __launch_bounds__(256, 2) void head_mma_k(
    const float* __restrict__ A, const float* __restrict__ W,
    const float* __restrict__ bias, float* __restrict__ C, int M) {
    extern __shared__ uint32_t hsm[];
    uint32_t* sAb = hsm;
    uint32_t* sBb = hsm + 8192;

    const int tid = threadIdx.x;
    const int lane = tid & 31;
    const int wid = tid >> 5;
    const int wm = wid >> 2, wn = wid & 3;
    const int row0 = blockIdx.y * 128;

    const int c4 = (tid & 7) * 4;
    const int rbase = tid >> 3;
    const int bn4 = (tid & 15) * 4;
    const int bkbase = tid >> 4;

    float acc[4][2][4];
#pragma unroll
    for (int i = 0; i < 4; i++)
#pragma unroll
        for (int j = 0; j < 2; j++)
#pragma unroll
            for (int t = 0; t < 4; t++) acc[i][j][t] = 0.0f;

    float4 av[4], bv[2];

    auto fetchH = [&](int k0) {
#pragma unroll
        for (int j = 0; j < 4; j++) {
            int gr = row0 + rbase + 32 * j;
            av[j] = (gr < M) ? *(const float4*)(A + (size_t)gr * 256 + k0 + c4)
                             : make_float4(0.f, 0.f, 0.f, 0.f);
        }
#pragma unroll
        for (int j = 0; j < 2; j++) {
            int k = bkbase + 16 * j;
            bv[j] = (bn4 < CLS) ? *(const float4*)(W + (size_t)(k0 + k) * CLS + bn4)
                                : make_float4(0.f, 0.f, 0.f, 0.f);
        }
    };
    auto scatH = [&](uint32_t* sa, uint32_t* sb) {
#pragma unroll
        for (int j = 0; j < 4; j++) {
            int r = rbase + 32 * j;
            int r16 = r & 15, mt = r >> 4;
            float vals[4] = {av[j].x, av[j].y, av[j].z, av[j].w};
#pragma unroll
            for (int t = 0; t < 4; t++) {
                int c = c4 + t;
                int kk = c >> 3, c8 = c & 7;
                int ln = (r16 & 7) * 4 + (c8 & 3);
                int sl = (r16 >> 3) | ((c8 >> 2) << 1);
                int tile = kk * 8 + mt;
                int lp = ln ^ ((tile >> 3) << 2);
                sa[(tile * 32 + lp) * 4 + sl] = tf32r(vals[t]);
            }
        }
#pragma unroll
        for (int j = 0; j < 2; j++) {
            int k = bkbase + 16 * j;
            int kk = k >> 3, k8 = k & 7;
            int sl = k8 >> 2, l4 = k8 & 3;
            float vals[4] = {bv[j].x, bv[j].y, bv[j].z, bv[j].w};
#pragma unroll
            for (int t = 0; t < 4; t++) {
                int n = bn4 + t;
                int nt = n >> 3, n8 = n & 7;
                int tile = kk * 8 + nt;
                int ln = n8 * 4 + l4;
                int lp = ln ^ ((tile & 7) << 2);
                sb[(tile * 32 + lp) * 2 + sl] = tf32r(vals[t]);
            }
        }
    };

    fetchH(0);
    scatH(sAb, sBb);
    __syncthreads();

#pragma unroll 1
    for (int ch = 0; ch < 8; ch++) {
        const int s = ch & 1;
        if (ch + 1 < 8) fetchH((ch + 1) << 5);
        const uint32_t* sa = sAb + s * 4096;
        const uint32_t* sb = sBb + s * 2048;
#pragma unroll
        for (int kk = 0; kk < 4; kk++) {
            uint32_t af[4][4];
            uint32_t bf[2][2];
#pragma unroll
            for (int im = 0; im < 4; im++) {
                int tile = kk * 8 + wm * 4 + im;
                int lp = lane ^ ((tile >> 3) << 2);
                uint4 u = *(const uint4*)(sa + (tile * 32 + lp) * 4);
                af[im][0] = u.x; af[im][1] = u.y; af[im][2] = u.z; af[im][3] = u.w;
            }
#pragma unroll
            for (int in = 0; in < 2; in++) {
                int tile = kk * 8 + wn * 2 + in;
                int lp = lane ^ ((tile & 7) << 2);
                uint2 u = *(const uint2*)(sb + (tile * 32 + lp) * 2);
                bf[in][0] = u.x; bf[in][1] = u.y;
            }
#pragma unroll
            for (int im = 0; im < 4; im++)
#pragma unroll
                for (int in = 0; in < 2; in++)
                    asm volatile(
                        "mma.sync.aligned.m16n8k8.row.col.f32.tf32.tf32.f32 "
                        "{%0,%1,%2,%3}, {%4,%5,%6,%7}, {%8,%9}, {%0,%1,%2,%3};"
                        : "+f"(acc[im][in][0]), "+f"(acc[im][in][1]),
                          "+f"(acc[im][in][2]), "+f"(acc[im][in][3])
                        : "r"(af[im][0]), "r"(af[im][1]), "r"(af[im][2]), "r"(af[im][3]),
                          "r"(bf[in][0]), "r"(bf[in][1]));
        }
        if (ch + 1 < 8) scatH(sAb + (s ^ 1) * 4096, sBb + (s ^ 1) * 2048);
        __syncthreads();
    }

#pragma unroll
    for (int im = 0; im < 4; im++) {
        int rl = row0 + wm * 64 + im * 16 + (lane >> 2);
        int rh = rl + 8;
#pragma unroll
        for (int in = 0; in < 2; in++) {
            int cc = wn * 16 + in * 8 + (lane & 3) * 2;
            if (cc >= CLS) continue;
            float b0 = bias[cc], b1 = bias[cc + 1];
            if (rl < M) {
                float2 v = make_float2(acc[im][in][0] + b0, acc[im][in][1] + b1);
                *(float2*)(C + (size_t)rl * CLS + cc) = v;
            }
            if (rh < M) {
                float2 v = make_float2(acc[im][in][2] + b0, acc[im][in][3] + b1);
                *(float2*)(C + (size_t)rh * CLS + cc) = v;
            }
        }
    }
}

// ---------------- CSR build ----------------
__global__ void zero_k(float* __restrict__ p, int n) {
    int i = blockIdx.x * blockDim.x + threadIdx.x;
    if (i < n) p[i] = 0.0f;
}
__global__ void zeroi_k(int* __restrict__ p, int n) {
    int i = blockIdx.x * blockDim.x + threadIdx.x;
    if (i < n) p[i] = 0;
}
__global__ void zstats_k() {
    int i = threadIdx.x;  // <<<1, D>>>
    g_sum[i] = 0.0f;
    g_sumsq[i] = 0.0f;
}

__global__ void deg_k(const int* __restrict__ src, const int* __restrict__ dst, int E) {
    int e = blockIdx.x * blockDim.x + threadIdx.x;
    if (e < E) {
        atomicAdd(&g_degout[src[e]], 1.0f);
        atomicAdd(&g_degin[dst[e]], 1.0f);
        atomicAdd(&g_cnt[dst[e]], 1);
    }
}

__global__ void norm_k(int n) {
    int i = blockIdx.x * blockDim.x + threadIdx.x;
    if (i < n) {
        g_ns[i] = rsqrtf(fmaxf(g_degout[i], 1.0f));
        g_nd[i] = rsqrtf(fmaxf(g_degin[i], 1.0f));
    }
}

__global__ void scan1_k(int Nn) {
    __shared__ int sh[256];
    int i = blockIdx.x * 256 + threadIdx.x;
    int v = (i < Nn) ? g_cnt[i] : 0;
    sh[threadIdx.x] = v;
    __syncthreads();
    for (int off = 1; off < 256; off <<= 1) {
        int t = (threadIdx.x >= off) ? sh[threadIdx.x - off] : 0;
        __syncthreads();
        sh[threadIdx.x] += t;
        __syncthreads();
    }
    if (i < Nn) g_rowptr[i] = sh[threadIdx.x] - v;
    if (threadIdx.x == 255) g_bsum[blockIdx.x] = sh[255];
}

__global__ void scan2_k(int nb) {
    __shared__ int sh[256];
    int v = (threadIdx.x < nb) ? g_bsum[threadIdx.x] : 0;
    sh[threadIdx.x] = v;
    __syncthreads();
    for (int off = 1; off < 256; off <<= 1) {
        int t = (threadIdx.x >= off) ? sh[threadIdx.x - off] : 0;
        __syncthreads();
        sh[threadIdx.x] += t;
        __syncthreads();
    }
    g_boff[threadIdx.x] = sh[threadIdx.x] - v;
}

__global__ void scan3_k(int Nn, int E) {
    int i = blockIdx.x * 256 + threadIdx.x;
    if (i < Nn) {
        int r = g_rowptr[i] + g_boff[blockIdx.x];
        g_rowptr[i] = r;
        g_cursor[i] = r;
    }
    if (i == 0) g_rowptr[Nn] = E;
}

__global__ void fill_k(const int* __restrict__ src, const int* __restrict__ dst, int E) {
    int e = blockIdx.x * blockDim.x + threadIdx.x;
    if (e < E) {
        int pos = atomicAdd(&g_cursor[dst[e]], 1);
        g_esrc[pos] = src[e];
    }
}

// ---------------- CSR gather SpMM (fp16 in/out, fp32 accum) ----------------
__global__ __launch_bounds__(256) void spmmh_k(const __half* __restrict__ X,
                                               __half* __restrict__ Mo, int Nn) {
    int node = blockIdx.x * 4 + (threadIdx.x >> 6);
    if (node >= Nn) return;
    int c0 = (threadIdx.x & 63) * 4;
    int beg = g_rowptr[node], end = g_rowptr[node + 1];
    float a0 = 0.f, a1 = 0.f, a2 = 0.f, a3 = 0.f;
    for (int j = beg; j < end; j++) {
        int s = g_esrc[j];
        float sc = g_ns[s];
        uint2 u = *(const uint2*)(X + (size_t)s * D + c0);
        float2 f0 = __half22float2(*(__half2*)&u.x);
        float2 f1 = __half22float2(*(__half2*)&u.y);
        a0 += f0.x * sc; a1 += f0.y * sc; a2 += f1.x * sc; a3 += f1.y * sc;
    }
    float nd = g_nd[node];
    __half2 o0 = __floats2half2_rn(a0 * nd, a1 * nd);
    __half2 o1 = __floats2half2_rn(a2 * nd, a3 * nd);
    uint2 o;
    o.x = *(uint32_t*)&o0;
    o.y = *(uint32_t*)&o1;
    *(uint2*)(Mo + (size_t)node * D + c0) = o;
}

// ---------------- batchnorm finalize + apply (fp16) ----------------
__global__ void bnfin_k(const float* __restrict__ gamma, const float* __restrict__ beta,
                        float invN) {
    int c = threadIdx.x;
    float mean = g_sum[c] * invN;
    float var = g_sumsq[c] * invN - mean * mean;
    float sc = gamma[c] * rsqrtf(var + 1e-5f);
    g_scale[c] = sc;
    g_shift[c] = beta[c] - mean * sc;
}

__device__ __forceinline__ float elu1(float v) { return v > 0.0f ? v : expm1f(v); }

__global__ void bnapplyh_k(uint4* __restrict__ X, int n8) {
    int i = blockIdx.x * blockDim.x + threadIdx.x;
    if (i >= n8) return;
    int c = (i & 31) * 8;
    uint4 u = X[i];
    __half2* h = (__half2*)&u;
#pragma unroll
    for (int t = 0; t < 4; t++) {
        float2 f = __half22float2(h[t]);
        f.x = elu1(f.x * g_scale[c + 2 * t] + g_shift[c + 2 * t]);
        f.y = elu1(f.y * g_scale[c + 2 * t + 1] + g_shift[c + 2 * t + 1]);
        h[t] = __floats2half2_rn(f.x, f.y);
    }
    X[i] = u;
}

// ---------------- host orchestration ----------------
static inline int cdiv(int a, int b) { return (a + b - 1) / b; }

extern "C" void kernel_launch(void* const* d_in, const int* in_sizes, int n_in,
                              void* d_out, int out_size) {
    const float* feat  = (const float*)d_in[0];
    const int*   src   = (const int*)d_in[1];
    const int*   dst   = (const int*)d_in[2];
    const float* W_fc  = (const float*)d_in[3];
    const float* b_fc  = (const float*)d_in[4];
    const float* W1    = (const float*)d_in[5];
    const float* b1    = (const float*)d_in[6];
    const float* W2    = (const float*)d_in[7];
    const float* b2    = (const float*)d_in[8];
    const float* W3    = (const float*)d_in[9];
    const float* b3    = (const float*)d_in[10];
    const float* gamma = (const float*)d_in[11];
    const float* beta  = (const float*)d_in[12];
    const float* W_lin = (const float*)d_in[13];
    const float* b_lin = (const float*)d_in[14];
    float* out = (float*)d_out;

    int N = in_sizes[0] / F;  // 50000
    int E = in_sizes[1];      // 300000

    cudaFuncSetAttribute(h_gemm_t<0, 1>, cudaFuncAttributeMaxDynamicSharedMemorySize, GEMM_SMEM);
    cudaFuncSetAttribute(h_gemm_t<1, 1>, cudaFuncAttributeMaxDynamicSharedMemorySize, GEMM_SMEM);
    cudaFuncSetAttribute(h_gemm_t<1, 0>, cudaFuncAttributeMaxDynamicSharedMemorySize, GEMM_SMEM);
    cudaFuncSetAttribute(head_mma_k, cudaFuncAttributeMaxDynamicSharedMemorySize, HEAD_SMEM);

    __half *pXh, *pYh, *pMh, *pWth;
    float *pDegO, *pDegI;
    int *pCnt;
    cudaGetSymbolAddress((void**)&pXh, g_Xh);
    cudaGetSymbolAddress((void**)&pYh, g_Yh);
    cudaGetSymbolAddress((void**)&pMh, g_Mh);
    cudaGetSymbolAddress((void**)&pWth, g_Wth);
    cudaGetSymbolAddress((void**)&pDegO, g_degout);
    cudaGetSymbolAddress((void**)&pDegI, g_degin);
    cudaGetSymbolAddress((void**)&pCnt, g_cnt);

    const int ND = N * D;
    const int TB = 256;
    const int nb = cdiv(N, 256);
    const dim3 ggrid(2, cdiv(N, 128));
    const dim3 hgrid(1, cdiv(N, 128));
    const dim3 tthr(32, 8);
    const int sgrid = cdiv(N, 4);

    // ---- FC first (independent of graph) so the FC GEMM is launch #4 for ncu ----
    wt_k<<<dim3(F / 32, 8), tthr>>>(W_fc, pWth, F);                          // 1
    zero_k<<<cdiv(N, TB), TB>>>(pDegO, N);                                   // 2
    zero_k<<<cdiv(N, TB), TB>>>(pDegI, N);                                   // 3
    h_gemm_t<0, 1><<<ggrid, 256, GEMM_SMEM>>>(feat, pWth, b_fc, pXh, N, F, 0);  // 4 (profiled)

    // ---- degree norms + CSR build ----
    zeroi_k<<<cdiv(N, TB), TB>>>(pCnt, N);
    deg_k<<<cdiv(E, TB), TB>>>(src, dst, E);
    norm_k<<<cdiv(N, TB), TB>>>(N);
    scan1_k<<<nb, 256>>>(N);
    scan2_k<<<1, 256>>>(nb);
    scan3_k<<<nb, 256>>>(N, E);
    fill_k<<<cdiv(E, TB), TB>>>(src, dst, E);

    // ---- layer 1 ----
    spmmh_k<<<sgrid, 256>>>(pXh, pMh, N);
    wt_k<<<dim3(D / 32, 8), tthr>>>(W1, pWth, D);
    zstats_k<<<1, D>>>();
    h_gemm_t<1, 1><<<ggrid, 256, GEMM_SMEM>>>(pMh, pWth, b1, pYh, N, D, 1);
    bnfin_k<<<1, D>>>(gamma, beta, 1.0f / (float)N);
    bnapplyh_k<<<cdiv(ND / 8, TB), TB>>>((uint4*)pYh, ND / 8);

    // ---- layer 2 ----
    spmmh_k<<<sgrid, 256>>>(pYh, pMh, N);
    wt_k<<<dim3(D / 32, 8), tthr>>>(W2, pWth, D);
    zstats_k<<<1, D>>>();
    h_gemm_t<1, 1><<<ggrid, 256, GEMM_SMEM>>>(pMh, pWth, b2, pXh, N, D, 1);
    bnfin_k<<<1, D>>>(gamma, beta, 1.0f / (float)N);
    bnapplyh_k<<<cdiv(ND / 8, TB), TB>>>((uint4*)pXh, ND / 8);

    // ---- layer 3: gconv -> out[0 : N*D] fp32 ----
    spmmh_k<<<sgrid, 256>>>(pXh, pMh, N);
    wt_k<<<dim3(D / 32, 8), tthr>>>(W3, pWth, D);
    h_gemm_t<1, 0><<<ggrid, 256, GEMM_SMEM>>>(pMh, pWth, b3, out, N, D, 0);

    // ---- head: logits = x @ W_lin + b_lin ----
    head_mma_k<<<hgrid, 256, HEAD_SMEM>>>(out, W_lin, b_lin, out + (size_t)N * D, N);
}